// round 6
// baseline (speedup 1.0000x reference)
#include <cuda_runtime.h>
#include <cuda_bf16.h>
#include <cstdint>
#include <math.h>

#define N_NODES 100000
#define N_EDGES 3200000
#define D_IN    512
#define D_OUT   256
#define NB1     ((N_NODES + 1023) / 1024)   // 98 scan blocks

// Scratch (no cudaMalloc allowed)
__device__ __align__(16) float g_presup[(size_t)N_NODES * D_OUT];   // 102.4 MB
__device__ float g_colsum[D_OUT];
__device__ __align__(16) __nv_bfloat16 g_Wth[(size_t)D_OUT * D_IN]; // W^T hi [n][k]
__device__ __align__(16) __nv_bfloat16 g_Wtl[(size_t)D_OUT * D_IN]; // W^T lo [n][k]
__device__ __align__(16) __nv_bfloat16 g_xh[(size_t)N_NODES * D_IN]; // x hi [m][k] 102.4MB
__device__ __align__(16) __nv_bfloat16 g_xl[(size_t)N_NODES * D_IN]; // x lo [m][k] 102.4MB
// CSR binning scratch
__device__ int   g_counts[N_NODES];
__device__ int   g_rowptr[N_NODES + 1];
__device__ int   g_cursor[N_NODES];
__device__ int   g_blocksums[128];
__device__ __align__(16) int2 g_csr_pair[N_EDGES];   // (col, val bits)

__device__ __forceinline__ uint32_t smem_u32(const void* p) {
    uint32_t a;
    asm("{ .reg .u64 t; cvta.to.shared.u64 t, %1; cvt.u32.u64 %0, t; }" : "=r"(a) : "l"(p));
    return a;
}
__device__ __forceinline__ uint32_t pack_bf2(__nv_bfloat16 a, __nv_bfloat16 b) {
    __nv_bfloat162 t = __halves2bfloat162(a, b);
    return *reinterpret_cast<uint32_t*>(&t);
}
__device__ __forceinline__ void ldmatrix_x4(uint32_t* r, uint32_t addr) {
    asm volatile("ldmatrix.sync.aligned.m8n8.x4.shared.b16 {%0,%1,%2,%3}, [%4];"
                 : "=r"(r[0]), "=r"(r[1]), "=r"(r[2]), "=r"(r[3]) : "r"(addr));
}
__device__ __forceinline__ void mma_bf16(float* d, const uint32_t* a, const uint32_t* b) {
    asm volatile(
        "mma.sync.aligned.m16n8k16.row.col.f32.bf16.bf16.f32 "
        "{%0,%1,%2,%3}, {%4,%5,%6,%7}, {%8,%9}, {%0,%1,%2,%3};"
        : "+f"(d[0]), "+f"(d[1]), "+f"(d[2]), "+f"(d[3])
        : "r"(a[0]), "r"(a[1]), "r"(a[2]), "r"(a[3]), "r"(b[0]), "r"(b[1]));
}
__device__ __forceinline__ void cp_async16(uint32_t dst, const void* src) {
    asm volatile("cp.async.cg.shared.global [%0], [%1], 16;"
                 :: "r"(dst), "l"(__cvta_generic_to_global(src)) : "memory");
}
__device__ __forceinline__ void cp_async16z(uint32_t dst, const void* src, int sz) {
    asm volatile("cp.async.cg.shared.global [%0], [%1], 16, %2;"
                 :: "r"(dst), "l"(__cvta_generic_to_global(src)), "r"(sz) : "memory");
}
#define CP_COMMIT() asm volatile("cp.async.commit_group;" ::: "memory")

// ===========================================================================
// 0a) W transpose + hi/lo bf16 split
// ===========================================================================
__global__ __launch_bounds__(256) void conv_w_kernel(const float* __restrict__ W) {
    int idx = blockIdx.x * 256 + threadIdx.x;
    if (idx >= D_IN * D_OUT) return;
    int k = idx / D_OUT, n = idx % D_OUT;
    float v = W[idx];
    __nv_bfloat16 h = __float2bfloat16_rn(v);
    __nv_bfloat16 l = __float2bfloat16_rn(v - __bfloat162float(h));
    g_Wth[(size_t)n * D_IN + k] = h;
    g_Wtl[(size_t)n * D_IN + k] = l;
}

// ===========================================================================
// 0b) x hi/lo bf16 split (streaming, same layout)
// ===========================================================================
__global__ __launch_bounds__(256) void conv_x_kernel(const float* __restrict__ x) {
    size_t i = (size_t)blockIdx.x * 256 + threadIdx.x;   // over float4s
    if (i >= (size_t)N_NODES * D_IN / 4) return;
    float4 a = __ldg((const float4*)x + i);
    __nv_bfloat16 h0 = __float2bfloat16_rn(a.x), h1 = __float2bfloat16_rn(a.y);
    __nv_bfloat16 h2 = __float2bfloat16_rn(a.z), h3 = __float2bfloat16_rn(a.w);
    __nv_bfloat16 l0 = __float2bfloat16_rn(a.x - __bfloat162float(h0));
    __nv_bfloat16 l1 = __float2bfloat16_rn(a.y - __bfloat162float(h1));
    __nv_bfloat16 l2 = __float2bfloat16_rn(a.z - __bfloat162float(h2));
    __nv_bfloat16 l3 = __float2bfloat16_rn(a.w - __bfloat162float(h3));
    ((uint2*)g_xh)[i] = make_uint2(pack_bf2(h0, h1), pack_bf2(h2, h3));
    ((uint2*)g_xl)[i] = make_uint2(pack_bf2(l0, l1), pack_bf2(l2, l3));
}

// ===========================================================================
// 1) GEMM: pre_sup = x @ W, pure cp.async 3-stage pipeline, bf16 hi/lo MMA
// ===========================================================================
#define BM 128
#define BN 128
#define BK 32
#define NKC (D_IN / BK)     // 16 chunks
#define ROW_B 80
#define ST_A_HI 0
#define ST_A_LO 10240
#define ST_B_HI 20480
#define ST_B_LO 30720
#define STAGE_B 40960
#define STAGES 3
#define SM_TOTAL (STAGES * STAGE_B)   // 122880

__global__ __launch_bounds__(256, 1) void gemm_tc_kernel() {
    extern __shared__ __align__(16) char smem[];
    const uint32_t sbase = smem_u32(smem);

    const int tid = threadIdx.x;
    const int wid = tid >> 5;
    const int lane = tid & 31;
    const int n0 = blockIdx.x * BN;    // grid.x = 2: both N-blocks of an m-tile adjacent
    const int m0 = blockIdx.y * BM;
    const int warp_m = (wid & 1) * 64;
    const int warp_n = (wid >> 1) * 32;

    float acc[4][4][4];
#pragma unroll
    for (int i = 0; i < 4; i++)
#pragma unroll
        for (int j = 0; j < 4; j++)
#pragma unroll
            for (int t = 0; t < 4; t++) acc[i][j][t] = 0.f;

    const uint32_t aLane = (uint32_t)((warp_m + (lane & 15)) * ROW_B + ((lane >> 4) << 4));
    const uint32_t bLane = (uint32_t)((warp_n + (lane & 7)) * ROW_B + ((lane >> 3) << 4));

    // per-thread load mapping: 8 cp.async of 16B; tile = idx>>9, sub = idx&511
    auto load = [&](int kc, int st) {
        const int k0 = kc * BK;
        const uint32_t stb = sbase + st * STAGE_B;
#pragma unroll
        for (int i = 0; i < 8; i++) {
            int idx = tid + i * 256;       // 0..2047
            int tile = idx >> 9;           // 0:A_HI 1:A_LO 2:B_HI 3:B_LO
            int sub = idx & 511;
            int row = sub >> 2;
            int ch  = sub & 3;
            uint32_t off = (uint32_t)(row * ROW_B + ch * 16);
            if (tile == 0) {
                int m = m0 + row;
                cp_async16z(stb + ST_A_HI + off,
                            g_xh + (size_t)m * D_IN + k0 + ch * 8,
                            m < N_NODES ? 16 : 0);
            } else if (tile == 1) {
                int m = m0 + row;
                cp_async16z(stb + ST_A_LO + off,
                            g_xl + (size_t)m * D_IN + k0 + ch * 8,
                            m < N_NODES ? 16 : 0);
            } else if (tile == 2) {
                cp_async16(stb + ST_B_HI + off,
                           g_Wth + (size_t)(n0 + row) * D_IN + k0 + ch * 8);
            } else {
                cp_async16(stb + ST_B_LO + off,
                           g_Wtl + (size_t)(n0 + row) * D_IN + k0 + ch * 8);
            }
        }
        CP_COMMIT();
    };

    // prologue: fill all 3 stages
    load(0, 0);
    load(1, 1);
    load(2, 2);

    for (int kc = 0; kc < NKC; kc++) {
        const int cur = kc % 3;
        const uint32_t base = sbase + cur * STAGE_B;

        asm volatile("cp.async.wait_group 2;" ::: "memory");
        __syncthreads();

        uint32_t bh[4][4], bl[4][4];
#pragma unroll
        for (int nt = 0; nt < 4; nt++) {
            ldmatrix_x4(bh[nt], base + ST_B_HI + bLane + nt * 8 * ROW_B);
            ldmatrix_x4(bl[nt], base + ST_B_LO + bLane + nt * 8 * ROW_B);
        }
#pragma unroll
        for (int ks = 0; ks < 2; ks++) {
            uint32_t ah[4][4], al[4][4];
#pragma unroll
            for (int mt = 0; mt < 4; mt++) {
                ldmatrix_x4(ah[mt], base + ST_A_HI + aLane + mt * 16 * ROW_B + ks * 32);
                ldmatrix_x4(al[mt], base + ST_A_LO + aLane + mt * 16 * ROW_B + ks * 32);
            }
#pragma unroll
            for (int mt = 0; mt < 4; mt++) {
#pragma unroll
                for (int nt = 0; nt < 4; nt++) {
                    uint32_t bhp[2] = {bh[nt][ks * 2], bh[nt][ks * 2 + 1]};
                    uint32_t blp[2] = {bl[nt][ks * 2], bl[nt][ks * 2 + 1]};
                    mma_bf16(acc[mt][nt], ah[mt], bhp);
                    mma_bf16(acc[mt][nt], ah[mt], blp);
                    mma_bf16(acc[mt][nt], al[mt], bhp);
                }
            }
        }
        __syncthreads();          // all warps done reading stage cur
        if (kc + 3 < NKC) load(kc + 3, cur);
        else              CP_COMMIT();   // keep group accounting uniform
    }

    // epilogue
    const int mrow = m0 + warp_m + (lane >> 2);
    const int ncol = n0 + warp_n + (lane & 3) * 2;
#pragma unroll
    for (int mt = 0; mt < 4; mt++) {
#pragma unroll
        for (int nt = 0; nt < 4; nt++) {
            int m = mrow + mt * 16;
            int n = ncol + nt * 8;
            if (m < N_NODES)
                *(float2*)(g_presup + (size_t)m * D_OUT + n) =
                    make_float2(acc[mt][nt][0], acc[mt][nt][1]);
            if (m + 8 < N_NODES)
                *(float2*)(g_presup + (size_t)(m + 8) * D_OUT + n) =
                    make_float2(acc[mt][nt][2], acc[mt][nt][3]);
        }
    }
}

// ===========================================================================
// 2a) CSR binning: count -> scan -> scatter
// ===========================================================================
__global__ __launch_bounds__(1024) void zero_counts_kernel() {
    int i = blockIdx.x * 1024 + threadIdx.x;
    if (i < N_NODES) g_counts[i] = 0;
}

__global__ __launch_bounds__(256) void count_kernel(const int* __restrict__ erow) {
    int e = blockIdx.x * 256 + threadIdx.x;
    if (e < N_EDGES) atomicAdd(&g_counts[__ldg(erow + e)], 1);
}

__global__ __launch_bounds__(1024) void scan1_kernel() {
    const int tid = threadIdx.x, lane = tid & 31, wid = tid >> 5;
    const int i = blockIdx.x * 1024 + tid;
    int v = (i < N_NODES) ? g_counts[i] : 0;
    int inc = v;
#pragma unroll
    for (int d = 1; d < 32; d <<= 1) {
        int t = __shfl_up_sync(~0u, inc, d);
        if (lane >= d) inc += t;
    }
    __shared__ int ws[32];
    if (lane == 31) ws[wid] = inc;
    __syncthreads();
    if (wid == 0) {
        int w = ws[lane];
#pragma unroll
        for (int d = 1; d < 32; d <<= 1) {
            int t = __shfl_up_sync(~0u, w, d);
            if (lane >= d) w += t;
        }
        ws[lane] = w;
    }
    __syncthreads();
    int base = wid ? ws[wid - 1] : 0;
    if (i < N_NODES) g_rowptr[i] = base + inc - v;
    if (tid == 0) g_blocksums[blockIdx.x] = ws[31];
}

__global__ __launch_bounds__(128) void scan2_kernel() {
    __shared__ int s[128];
    const int tid = threadIdx.x;
    s[tid] = (tid < NB1) ? g_blocksums[tid] : 0;
    __syncthreads();
    for (int d = 1; d < 128; d <<= 1) {
        int t = (tid >= d) ? s[tid - d] : 0;
        __syncthreads();
        s[tid] += t;
        __syncthreads();
    }
    g_blocksums[tid] = (tid > 0) ? s[tid - 1] : 0;
}

__global__ __launch_bounds__(1024) void scan3_kernel() {
    int i = blockIdx.x * 1024 + threadIdx.x;
    if (i < N_NODES) {
        int rp = g_rowptr[i] + g_blocksums[blockIdx.x];
        g_rowptr[i] = rp;
        g_cursor[i] = rp;
    }
    if (i == 0) g_rowptr[N_NODES] = N_EDGES;
}

__global__ __launch_bounds__(256) void scatter_kernel(const int* __restrict__ erow,
                                                      const int* __restrict__ ecol,
                                                      const float* __restrict__ evals) {
    int e = blockIdx.x * 256 + threadIdx.x;
    if (e >= N_EDGES) return;
    int r = __ldg(erow + e);
    int p = atomicAdd(&g_cursor[r], 1);
    g_csr_pair[p] = make_int2(__ldg(ecol + e), __float_as_int(__ldg(evals + e)));
}

// ===========================================================================
// 2b) SpMM CSR, fused bias + column sum-of-squares.
//     One warp per row (grid-strided), register accumulation, no f32 atomics
//     on the output; colsq accumulated in regs -> smem -> one REDG per column
//     per block.
// ===========================================================================
#define SPMM_BLOCKS 1568
__global__ __launch_bounds__(256) void spmm_csr_kernel(float* __restrict__ out,
                                                       const float* __restrict__ bias) {
    __shared__ float scs[256];
    const int tid = threadIdx.x;
    const int lane = tid & 31;
    scs[tid] = 0.f;
    __syncthreads();

    const int gw = (blockIdx.x * 256 + tid) >> 5;
    const int nw = (SPMM_BLOCKS * 256) >> 5;
    const int lo = lane * 2;                 // float4 index within a 256-col row
    const float4 bb0 = __ldg((const float4*)bias + lo);
    const float4 bb1 = __ldg((const float4*)bias + lo + 1);
    const float4* base = (const float4*)g_presup;

    float cs[8] = {0.f, 0.f, 0.f, 0.f, 0.f, 0.f, 0.f, 0.f};

    for (int r = gw; r < N_NODES; r += nw) {
        const int beg = __ldg(g_rowptr + r);
        const int end = __ldg(g_rowptr + r + 1);

        float4 A0 = make_float4(0.f, 0.f, 0.f, 0.f);
        float4 A1 = make_float4(0.f, 0.f, 0.f, 0.f);

        int e = beg;
        for (; e + 2 <= end; e += 2) {
            int2 pr0 = __ldg(g_csr_pair + e);
            int2 pr1 = __ldg(g_csr_pair + e + 1);
            float v0 = __int_as_float(pr0.y);
            float v1 = __int_as_float(pr1.y);
            const float4* s0 = base + (size_t)pr0.x * (D_OUT / 4) + lo;
            const float4* s1 = base + (size_t)pr1.x * (D_OUT / 4) + lo;
            float4 p00 = __ldg(s0), p01 = __ldg(s0 + 1);
            float4 p10 = __ldg(s1), p11 = __ldg(s1 + 1);
            A0.x = fmaf(v0, p00.x, A0.x); A0.y = fmaf(v0, p00.y, A0.y);
            A0.z = fmaf(v0, p00.z, A0.z); A0.w = fmaf(v0, p00.w, A0.w);
            A1.x = fmaf(v0, p01.x, A1.x); A1.y = fmaf(v0, p01.y, A1.y);
            A1.z = fmaf(v0, p01.z, A1.z); A1.w = fmaf(v0, p01.w, A1.w);
            A0.x = fmaf(v1, p10.x, A0.x); A0.y = fmaf(v1, p10.y, A0.y);
            A0.z = fmaf(v1, p10.z, A0.z); A0.w = fmaf(v1, p10.w, A0.w);
            A1.x = fmaf(v1, p11.x, A1.x); A1.y = fmaf(v1, p11.y, A1.y);
            A1.z = fmaf(v1, p11.z, A1.z); A1.w = fmaf(v1, p11.w, A1.w);
        }
        if (e < end) {
            int2 pr0 = __ldg(g_csr_pair + e);
            float v0 = __int_as_float(pr0.y);
            const float4* s0 = base + (size_t)pr0.x * (D_OUT / 4) + lo;
            float4 p00 = __ldg(s0), p01 = __ldg(s0 + 1);
            A0.x = fmaf(v0, p00.x, A0.x); A0.y = fmaf(v0, p00.y, A0.y);
            A0.z = fmaf(v0, p00.z, A0.z); A0.w = fmaf(v0, p00.w, A0.w);
            A1.x = fmaf(v0, p01.x, A1.x); A1.y = fmaf(v0, p01.y, A1.y);
            A1.z = fmaf(v0, p01.z, A1.z); A1.w = fmaf(v0, p01.w, A1.w);
        }

        // bias add (matches reference agg + b, before norm)
        A0.x += bb0.x; A0.y += bb0.y; A0.z += bb0.z; A0.w += bb0.w;
        A1.x += bb1.x; A1.y += bb1.y; A1.z += bb1.z; A1.w += bb1.w;

        float4* dst = (float4*)(out + (size_t)r * D_OUT) + lo;
        dst[0] = A0;
        dst[1] = A1;

        cs[0] = fmaf(A0.x, A0.x, cs[0]); cs[1] = fmaf(A0.y, A0.y, cs[1]);
        cs[2] = fmaf(A0.z, A0.z, cs[2]); cs[3] = fmaf(A0.w, A0.w, cs[3]);
        cs[4] = fmaf(A1.x, A1.x, cs[4]); cs[5] = fmaf(A1.y, A1.y, cs[5]);
        cs[6] = fmaf(A1.z, A1.z, cs[6]); cs[7] = fmaf(A1.w, A1.w, cs[7]);
    }

    // per-warp partials -> smem (8 warps share the 256 column slots)
#pragma unroll
    for (int j = 0; j < 8; j++)
        atomicAdd(&scs[lane * 8 + j], cs[j]);
    __syncthreads();
    atomicAdd(&g_colsum[tid], scs[tid]);
}

__global__ void zero_colsum_kernel() { g_colsum[threadIdx.x] = 0.f; }

// ===========================================================================
// 3) Finalize: out = softplus(out / max(col_norm, 1e-12))   (bias already in)
// ===========================================================================
__global__ __launch_bounds__(256) void finalize_kernel(float* __restrict__ out) {
    const int c = threadIdx.x;
    const float inv = 1.f / fmaxf(sqrtf(g_colsum[c]), 1e-12f);
    for (int r = blockIdx.x; r < N_NODES; r += gridDim.x) {
        float v = out[(size_t)r * D_OUT + c] * inv;
        out[(size_t)r * D_OUT + c] = fmaxf(v, 0.f) + log1pf(__expf(-fabsf(v)));
    }
}

// ===========================================================================
extern "C" void kernel_launch(void* const* d_in, const int* in_sizes, int n_in,
                              void* d_out, int out_size) {
    const float* x     = (const float*)d_in[0];
    const int*   erow  = (const int*)  d_in[1];
    const int*   ecol  = (const int*)  d_in[2];
    const float* evals = (const float*)d_in[3];
    const float* W     = (const float*)d_in[4];
    const float* b     = (const float*)d_in[5];
    float* out = (float*)d_out;

    cudaFuncSetAttribute(gemm_tc_kernel,
                         cudaFuncAttributeMaxDynamicSharedMemorySize, SM_TOTAL);

    zero_colsum_kernel<<<1, D_OUT>>>();
    conv_w_kernel<<<(D_IN * D_OUT + 255) / 256, 256>>>(W);
    conv_x_kernel<<<(int)(((size_t)N_NODES * D_IN / 4 + 255) / 256), 256>>>(x);

    // CSR binning (independent of GEMM)
    zero_counts_kernel<<<NB1, 1024>>>();
    count_kernel<<<(N_EDGES + 255) / 256, 256>>>(erow);
    scan1_kernel<<<NB1, 1024>>>();
    scan2_kernel<<<1, 128>>>();
    scan3_kernel<<<NB1, 1024>>>();
    scatter_kernel<<<(N_EDGES + 255) / 256, 256>>>(erow, ecol, evals);

    // GEMM
    dim3 ggrid(D_OUT / BN, (N_NODES + BM - 1) / BM);
    gemm_tc_kernel<<<ggrid, 256, SM_TOTAL>>>();

    // SpMM (CSR, fused bias + colsumsq)
    spmm_csr_kernel<<<SPMM_BLOCKS, 256>>>(out, b);

    finalize_kernel<<<4096, 256>>>(out);
}

// round 7
// speedup vs baseline: 1.0921x; 1.0921x over previous
#include <cuda_runtime.h>
#include <cuda_bf16.h>
#include <cstdint>
#include <math.h>

#define N_NODES 100000
#define N_EDGES 3200000
#define D_IN    512
#define D_OUT   256
#define NB1     ((N_NODES + 1023) / 1024)   // 98 scan blocks

// Scratch (no cudaMalloc allowed)
__device__ __align__(16) float g_presup[(size_t)N_NODES * D_OUT];   // 102.4 MB
__device__ float g_colsum[D_OUT];
__device__ __align__(16) __nv_bfloat16 g_Wth[(size_t)D_OUT * D_IN]; // W^T hi [n][k]
__device__ __align__(16) __nv_bfloat16 g_Wtl[(size_t)D_OUT * D_IN]; // W^T lo [n][k]
// CSR binning scratch
__device__ int   g_counts[N_NODES];
__device__ int   g_rowptr[N_NODES + 1];
__device__ int   g_cursor[N_NODES];
__device__ int   g_blocksums[128];
__device__ __align__(16) int2 g_csr_pair[N_EDGES];   // (col, val bits)

__device__ __forceinline__ uint32_t smem_u32(const void* p) {
    uint32_t a;
    asm("{ .reg .u64 t; cvta.to.shared.u64 t, %1; cvt.u32.u64 %0, t; }" : "=r"(a) : "l"(p));
    return a;
}
__device__ __forceinline__ uint32_t pack_bf2(__nv_bfloat16 a, __nv_bfloat16 b) {
    __nv_bfloat162 t = __halves2bfloat162(a, b);
    return *reinterpret_cast<uint32_t*>(&t);
}
__device__ __forceinline__ void ldmatrix_x4(uint32_t* r, uint32_t addr) {
    asm volatile("ldmatrix.sync.aligned.m8n8.x4.shared.b16 {%0,%1,%2,%3}, [%4];"
                 : "=r"(r[0]), "=r"(r[1]), "=r"(r[2]), "=r"(r[3]) : "r"(addr));
}
__device__ __forceinline__ void mma_bf16(float* d, const uint32_t* a, const uint32_t* b) {
    asm volatile(
        "mma.sync.aligned.m16n8k16.row.col.f32.bf16.bf16.f32 "
        "{%0,%1,%2,%3}, {%4,%5,%6,%7}, {%8,%9}, {%0,%1,%2,%3};"
        : "+f"(d[0]), "+f"(d[1]), "+f"(d[2]), "+f"(d[3])
        : "r"(a[0]), "r"(a[1]), "r"(a[2]), "r"(a[3]), "r"(b[0]), "r"(b[1]));
}
__device__ __forceinline__ void cp_async16(uint32_t dst, const void* src) {
    asm volatile("cp.async.cg.shared.global [%0], [%1], 16;"
                 :: "r"(dst), "l"(__cvta_generic_to_global(src)) : "memory");
}
#define CP_COMMIT() asm volatile("cp.async.commit_group;" ::: "memory")

// ===========================================================================
// 0) W transpose + hi/lo bf16 split
// ===========================================================================
__global__ __launch_bounds__(256) void conv_w_kernel(const float* __restrict__ W) {
    int idx = blockIdx.x * 256 + threadIdx.x;
    if (idx >= D_IN * D_OUT) return;
    int k = idx / D_OUT, n = idx % D_OUT;
    float v = W[idx];
    __nv_bfloat16 h = __float2bfloat16_rn(v);
    __nv_bfloat16 l = __float2bfloat16_rn(v - __bfloat162float(h));
    g_Wth[(size_t)n * D_IN + k] = h;
    g_Wtl[(size_t)n * D_IN + k] = l;
}

// ===========================================================================
// 1) GEMM: pre_sup = x @ W via mma.sync bf16 hi/lo, 2-stage cp.async pipeline
//    (round-5 version: A converted in-register, x read once via grid swizzle)
// ===========================================================================
#define BM 128
#define BN 128
#define BK 32
#define NKC (D_IN / BK)     // 16 chunks
#define ROW_B 80
#define ST_A_HI 0
#define ST_A_LO 10240
#define ST_B_HI 20480
#define ST_B_LO 30720
#define STAGE_B 40960
#define SM_TOTAL (2 * STAGE_B)   // 81920

__global__ __launch_bounds__(256, 1) void gemm_tc_kernel(const float* __restrict__ x) {
    extern __shared__ __align__(16) char smem[];
    const uint32_t sbase = smem_u32(smem);

    const int tid = threadIdx.x;
    const int wid = tid >> 5;
    const int lane = tid & 31;
    const int n0 = blockIdx.x * BN;    // grid.x = 2: both N-blocks of an m-tile adjacent
    const int m0 = blockIdx.y * BM;
    const int warp_m = (wid & 1) * 64;
    const int warp_n = (wid >> 1) * 32;

    const int a_row = tid >> 3;
    const int a_f4  = tid & 7;
    float4 areg[4];

    float acc[4][4][4];
#pragma unroll
    for (int i = 0; i < 4; i++)
#pragma unroll
        for (int j = 0; j < 4; j++)
#pragma unroll
            for (int t = 0; t < 4; t++) acc[i][j][t] = 0.f;

    const uint32_t aLane = (uint32_t)((warp_m + (lane & 15)) * ROW_B + ((lane >> 4) << 4));
    const uint32_t bLane = (uint32_t)((warp_n + (lane & 7)) * ROW_B + ((lane >> 3) << 4));

    auto ldgA = [&](int kc) {
        const int k0 = kc * BK;
#pragma unroll
        for (int i = 0; i < 4; i++) {
            int row = a_row + i * 32;
            int m = m0 + row;
            areg[i] = make_float4(0.f, 0.f, 0.f, 0.f);
            if (m < N_NODES)
                areg[i] = *(const float4*)(x + (size_t)m * D_IN + k0 + a_f4 * 4);
        }
    };
    auto stsA = [&](int st) {
        char* sb = smem + st * STAGE_B;
#pragma unroll
        for (int i = 0; i < 4; i++) {
            float4 a = areg[i];
            int row = a_row + i * 32;
            __nv_bfloat16 h0 = __float2bfloat16_rn(a.x), h1 = __float2bfloat16_rn(a.y);
            __nv_bfloat16 h2 = __float2bfloat16_rn(a.z), h3 = __float2bfloat16_rn(a.w);
            __nv_bfloat16 l0 = __float2bfloat16_rn(a.x - __bfloat162float(h0));
            __nv_bfloat16 l1 = __float2bfloat16_rn(a.y - __bfloat162float(h1));
            __nv_bfloat16 l2 = __float2bfloat16_rn(a.z - __bfloat162float(h2));
            __nv_bfloat16 l3 = __float2bfloat16_rn(a.w - __bfloat162float(h3));
            int off = row * ROW_B + a_f4 * 8;
            *(uint2*)(sb + ST_A_HI + off) = make_uint2(pack_bf2(h0, h1), pack_bf2(h2, h3));
            *(uint2*)(sb + ST_A_LO + off) = make_uint2(pack_bf2(l0, l1), pack_bf2(l2, l3));
        }
    };
    auto cpB = [&](int kc, int st) {
        const int k0 = kc * BK;
        const uint32_t stb = sbase + st * STAGE_B;
#pragma unroll
        for (int i = 0; i < 4; i++) {
            int idx = tid + i * 256;
            int sub = idx & 511;
            int row = sub >> 2;
            int ch  = sub & 3;
            uint32_t off = (uint32_t)(row * ROW_B + ch * 16);
            if (idx < 512)
                cp_async16(stb + ST_B_HI + off, g_Wth + (size_t)(n0 + row) * D_IN + k0 + ch * 8);
            else
                cp_async16(stb + ST_B_LO + off, g_Wtl + (size_t)(n0 + row) * D_IN + k0 + ch * 8);
        }
        CP_COMMIT();
    };

    // ---- prologue
    ldgA(0);
    cpB(0, 0);
    stsA(0);
    ldgA(1);
    cpB(1, 1);
    asm volatile("cp.async.wait_group 1;" ::: "memory");
    __syncthreads();

    for (int kc = 0; kc < NKC; kc++) {
        const int cur = kc & 1;
        const uint32_t base = sbase + cur * STAGE_B;

        uint32_t bh[4][4], bl[4][4];
#pragma unroll
        for (int nt = 0; nt < 4; nt++) {
            ldmatrix_x4(bh[nt], base + ST_B_HI + bLane + nt * 8 * ROW_B);
            ldmatrix_x4(bl[nt], base + ST_B_LO + bLane + nt * 8 * ROW_B);
        }
#pragma unroll
        for (int ks = 0; ks < 2; ks++) {
            uint32_t ah[4][4], al[4][4];
#pragma unroll
            for (int mt = 0; mt < 4; mt++) {
                ldmatrix_x4(ah[mt], base + ST_A_HI + aLane + mt * 16 * ROW_B + ks * 32);
                ldmatrix_x4(al[mt], base + ST_A_LO + aLane + mt * 16 * ROW_B + ks * 32);
            }
#pragma unroll
            for (int mt = 0; mt < 4; mt++) {
#pragma unroll
                for (int nt = 0; nt < 4; nt++) {
                    uint32_t bhp[2] = {bh[nt][ks * 2], bh[nt][ks * 2 + 1]};
                    uint32_t blp[2] = {bl[nt][ks * 2], bl[nt][ks * 2 + 1]};
                    mma_bf16(acc[mt][nt], ah[mt], bhp);
                    mma_bf16(acc[mt][nt], ah[mt], blp);
                    mma_bf16(acc[mt][nt], al[mt], bhp);
                }
            }
        }

        if (kc < NKC - 1) stsA(cur ^ 1);
        __syncthreads();
        if (kc < NKC - 2) {
            ldgA(kc + 2);
            cpB(kc + 2, cur);
        }
        if (kc < NKC - 1) {
            if (kc < NKC - 2)
                asm volatile("cp.async.wait_group 1;" ::: "memory");
            else
                asm volatile("cp.async.wait_group 0;" ::: "memory");
            __syncthreads();
        }
    }

    // ---- epilogue
    const int mrow = m0 + warp_m + (lane >> 2);
    const int ncol = n0 + warp_n + (lane & 3) * 2;
#pragma unroll
    for (int mt = 0; mt < 4; mt++) {
#pragma unroll
        for (int nt = 0; nt < 4; nt++) {
            int m = mrow + mt * 16;
            int n = ncol + nt * 8;
            if (m < N_NODES)
                *(float2*)(g_presup + (size_t)m * D_OUT + n) =
                    make_float2(acc[mt][nt][0], acc[mt][nt][1]);
            if (m + 8 < N_NODES)
                *(float2*)(g_presup + (size_t)(m + 8) * D_OUT + n) =
                    make_float2(acc[mt][nt][2], acc[mt][nt][3]);
        }
    }
}

// ===========================================================================
// 2a) CSR binning: count -> scan -> scatter
// ===========================================================================
__global__ __launch_bounds__(1024) void zero_counts_kernel() {
    int i = blockIdx.x * 1024 + threadIdx.x;
    if (i < N_NODES) g_counts[i] = 0;
}

__global__ __launch_bounds__(256) void count_kernel(const int* __restrict__ erow) {
    int e = blockIdx.x * 256 + threadIdx.x;
    if (e < N_EDGES) atomicAdd(&g_counts[__ldg(erow + e)], 1);
}

__global__ __launch_bounds__(1024) void scan1_kernel() {
    const int tid = threadIdx.x, lane = tid & 31, wid = tid >> 5;
    const int i = blockIdx.x * 1024 + tid;
    int v = (i < N_NODES) ? g_counts[i] : 0;
    int inc = v;
#pragma unroll
    for (int d = 1; d < 32; d <<= 1) {
        int t = __shfl_up_sync(~0u, inc, d);
        if (lane >= d) inc += t;
    }
    __shared__ int ws[32];
    if (lane == 31) ws[wid] = inc;
    __syncthreads();
    if (wid == 0) {
        int w = ws[lane];
#pragma unroll
        for (int d = 1; d < 32; d <<= 1) {
            int t = __shfl_up_sync(~0u, w, d);
            if (lane >= d) w += t;
        }
        ws[lane] = w;
    }
    __syncthreads();
    int base = wid ? ws[wid - 1] : 0;
    if (i < N_NODES) g_rowptr[i] = base + inc - v;
    if (tid == 0) g_blocksums[blockIdx.x] = ws[31];
}

__global__ __launch_bounds__(128) void scan2_kernel() {
    __shared__ int s[128];
    const int tid = threadIdx.x;
    s[tid] = (tid < NB1) ? g_blocksums[tid] : 0;
    __syncthreads();
    for (int d = 1; d < 128; d <<= 1) {
        int t = (tid >= d) ? s[tid - d] : 0;
        __syncthreads();
        s[tid] += t;
        __syncthreads();
    }
    g_blocksums[tid] = (tid > 0) ? s[tid - 1] : 0;
}

__global__ __launch_bounds__(1024) void scan3_kernel() {
    int i = blockIdx.x * 1024 + threadIdx.x;
    if (i < N_NODES) {
        int rp = g_rowptr[i] + g_blocksums[blockIdx.x];
        g_rowptr[i] = rp;
        g_cursor[i] = rp;
    }
    if (i == 0) g_rowptr[N_NODES] = N_EDGES;
}

__global__ __launch_bounds__(256) void scatter_kernel(const int* __restrict__ erow,
                                                      const int* __restrict__ ecol,
                                                      const float* __restrict__ evals) {
    int e = blockIdx.x * 256 + threadIdx.x;
    if (e >= N_EDGES) return;
    int r = __ldg(erow + e);
    int p = atomicAdd(&g_cursor[r], 1);
    g_csr_pair[p] = make_int2(__ldg(ecol + e), __float_as_int(__ldg(evals + e)));
}

// ===========================================================================
// 2b) SpMM CSR, fused bias + column sum-of-squares.
// ===========================================================================
#define SPMM_BLOCKS 1568
__global__ __launch_bounds__(256) void spmm_csr_kernel(float* __restrict__ out,
                                                       const float* __restrict__ bias) {
    __shared__ float scs[256];
    const int tid = threadIdx.x;
    const int lane = tid & 31;
    scs[tid] = 0.f;
    __syncthreads();

    const int gw = (blockIdx.x * 256 + tid) >> 5;
    const int nw = (SPMM_BLOCKS * 256) >> 5;
    const int lo = lane * 2;
    const float4 bb0 = __ldg((const float4*)bias + lo);
    const float4 bb1 = __ldg((const float4*)bias + lo + 1);
    const float4* base = (const float4*)g_presup;

    float cs[8] = {0.f, 0.f, 0.f, 0.f, 0.f, 0.f, 0.f, 0.f};

    for (int r = gw; r < N_NODES; r += nw) {
        const int beg = __ldg(g_rowptr + r);
        const int end = __ldg(g_rowptr + r + 1);

        float4 A0 = make_float4(0.f, 0.f, 0.f, 0.f);
        float4 A1 = make_float4(0.f, 0.f, 0.f, 0.f);

        int e = beg;
        for (; e + 2 <= end; e += 2) {
            int2 pr0 = __ldg(g_csr_pair + e);
            int2 pr1 = __ldg(g_csr_pair + e + 1);
            float v0 = __int_as_float(pr0.y);
            float v1 = __int_as_float(pr1.y);
            const float4* s0 = base + (size_t)pr0.x * (D_OUT / 4) + lo;
            const float4* s1 = base + (size_t)pr1.x * (D_OUT / 4) + lo;
            float4 p00 = __ldg(s0), p01 = __ldg(s0 + 1);
            float4 p10 = __ldg(s1), p11 = __ldg(s1 + 1);
            A0.x = fmaf(v0, p00.x, A0.x); A0.y = fmaf(v0, p00.y, A0.y);
            A0.z = fmaf(v0, p00.z, A0.z); A0.w = fmaf(v0, p00.w, A0.w);
            A1.x = fmaf(v0, p01.x, A1.x); A1.y = fmaf(v0, p01.y, A1.y);
            A1.z = fmaf(v0, p01.z, A1.z); A1.w = fmaf(v0, p01.w, A1.w);
            A0.x = fmaf(v1, p10.x, A0.x); A0.y = fmaf(v1, p10.y, A0.y);
            A0.z = fmaf(v1, p10.z, A0.z); A0.w = fmaf(v1, p10.w, A0.w);
            A1.x = fmaf(v1, p11.x, A1.x); A1.y = fmaf(v1, p11.y, A1.y);
            A1.z = fmaf(v1, p11.z, A1.z); A1.w = fmaf(v1, p11.w, A1.w);
        }
        if (e < end) {
            int2 pr0 = __ldg(g_csr_pair + e);
            float v0 = __int_as_float(pr0.y);
            const float4* s0 = base + (size_t)pr0.x * (D_OUT / 4) + lo;
            float4 p00 = __ldg(s0), p01 = __ldg(s0 + 1);
            A0.x = fmaf(v0, p00.x, A0.x); A0.y = fmaf(v0, p00.y, A0.y);
            A0.z = fmaf(v0, p00.z, A0.z); A0.w = fmaf(v0, p00.w, A0.w);
            A1.x = fmaf(v0, p01.x, A1.x); A1.y = fmaf(v0, p01.y, A1.y);
            A1.z = fmaf(v0, p01.z, A1.z); A1.w = fmaf(v0, p01.w, A1.w);
        }

        A0.x += bb0.x; A0.y += bb0.y; A0.z += bb0.z; A0.w += bb0.w;
        A1.x += bb1.x; A1.y += bb1.y; A1.z += bb1.z; A1.w += bb1.w;

        float4* dst = (float4*)(out + (size_t)r * D_OUT) + lo;
        dst[0] = A0;
        dst[1] = A1;

        cs[0] = fmaf(A0.x, A0.x, cs[0]); cs[1] = fmaf(A0.y, A0.y, cs[1]);
        cs[2] = fmaf(A0.z, A0.z, cs[2]); cs[3] = fmaf(A0.w, A0.w, cs[3]);
        cs[4] = fmaf(A1.x, A1.x, cs[4]); cs[5] = fmaf(A1.y, A1.y, cs[5]);
        cs[6] = fmaf(A1.z, A1.z, cs[6]); cs[7] = fmaf(A1.w, A1.w, cs[7]);
    }

#pragma unroll
    for (int j = 0; j < 8; j++)
        atomicAdd(&scs[lane * 8 + j], cs[j]);
    __syncthreads();
    atomicAdd(&g_colsum[tid], scs[tid]);
}

__global__ void zero_colsum_kernel() { g_colsum[threadIdx.x] = 0.f; }

// ===========================================================================
// 3) Finalize: out = softplus(out / max(col_norm, 1e-12))   (bias already in)
// ===========================================================================
__global__ __launch_bounds__(256) void finalize_kernel(float* __restrict__ out) {
    const int c = threadIdx.x;
    const float inv = 1.f / fmaxf(sqrtf(g_colsum[c]), 1e-12f);
    for (int r = blockIdx.x; r < N_NODES; r += gridDim.x) {
        float v = out[(size_t)r * D_OUT + c] * inv;
        out[(size_t)r * D_OUT + c] = fmaxf(v, 0.f) + log1pf(__expf(-fabsf(v)));
    }
}

// ===========================================================================
extern "C" void kernel_launch(void* const* d_in, const int* in_sizes, int n_in,
                              void* d_out, int out_size) {
    const float* x     = (const float*)d_in[0];
    const int*   erow  = (const int*)  d_in[1];
    const int*   ecol  = (const int*)  d_in[2];
    const float* evals = (const float*)d_in[3];
    const float* W     = (const float*)d_in[4];
    const float* b     = (const float*)d_in[5];
    float* out = (float*)d_out;

    cudaFuncSetAttribute(gemm_tc_kernel,
                         cudaFuncAttributeMaxDynamicSharedMemorySize, SM_TOTAL);

    zero_colsum_kernel<<<1, D_OUT>>>();
    conv_w_kernel<<<(D_IN * D_OUT + 255) / 256, 256>>>(W);

    // CSR binning (independent of GEMM)
    zero_counts_kernel<<<NB1, 1024>>>();
    count_kernel<<<(N_EDGES + 255) / 256, 256>>>(erow);
    scan1_kernel<<<NB1, 1024>>>();
    scan2_kernel<<<1, 128>>>();
    scan3_kernel<<<NB1, 1024>>>();
    scatter_kernel<<<(N_EDGES + 255) / 256, 256>>>(erow, ecol, evals);

    // GEMM (grid.x = N-blocks so both share the m-tile in L2)
    dim3 ggrid(D_OUT / BN, (N_NODES + BM - 1) / BM);
    gemm_tc_kernel<<<ggrid, 256, SM_TOTAL>>>(x);

    // SpMM (CSR, fused bias + colsumsq)
    spmm_csr_kernel<<<SPMM_BLOCKS, 256>>>(out, b);

    finalize_kernel<<<4096, 256>>>(out);
}

// round 8
// speedup vs baseline: 1.1874x; 1.0873x over previous
#include <cuda_runtime.h>
#include <cuda_bf16.h>
#include <cstdint>
#include <math.h>

#define N_NODES 100000
#define N_EDGES 3200000
#define D_IN    512
#define D_OUT   256
#define NB1     ((N_NODES + 1023) / 1024)   // 98 scan blocks

// Scratch (no cudaMalloc allowed)
__device__ __align__(16) float g_presup[(size_t)N_NODES * D_OUT];   // 102.4 MB
__device__ float g_colsum[D_OUT];
__device__ __align__(16) __nv_bfloat16 g_Wth[(size_t)D_OUT * D_IN]; // W^T hi [n][k]
__device__ __align__(16) __nv_bfloat16 g_Wtl[(size_t)D_OUT * D_IN]; // W^T lo [n][k]
// CSR binning scratch
__device__ int   g_counts[N_NODES];
__device__ int   g_rowptr[N_NODES + 1];
__device__ int   g_cursor[N_NODES];
__device__ int   g_blocksums[128];
__device__ __align__(16) int2 g_csr_pair[N_EDGES];   // (col, val bits)

__device__ __forceinline__ uint32_t smem_u32(const void* p) {
    uint32_t a;
    asm("{ .reg .u64 t; cvta.to.shared.u64 t, %1; cvt.u32.u64 %0, t; }" : "=r"(a) : "l"(p));
    return a;
}
__device__ __forceinline__ uint32_t pack_bf2(__nv_bfloat16 a, __nv_bfloat16 b) {
    __nv_bfloat162 t = __halves2bfloat162(a, b);
    return *reinterpret_cast<uint32_t*>(&t);
}
__device__ __forceinline__ void ldmatrix_x4(uint32_t* r, uint32_t addr) {
    asm volatile("ldmatrix.sync.aligned.m8n8.x4.shared.b16 {%0,%1,%2,%3}, [%4];"
                 : "=r"(r[0]), "=r"(r[1]), "=r"(r[2]), "=r"(r[3]) : "r"(addr));
}
__device__ __forceinline__ void mma_bf16(float* d, const uint32_t* a, const uint32_t* b) {
    asm volatile(
        "mma.sync.aligned.m16n8k16.row.col.f32.bf16.bf16.f32 "
        "{%0,%1,%2,%3}, {%4,%5,%6,%7}, {%8,%9}, {%0,%1,%2,%3};"
        : "+f"(d[0]), "+f"(d[1]), "+f"(d[2]), "+f"(d[3])
        : "r"(a[0]), "r"(a[1]), "r"(a[2]), "r"(a[3]), "r"(b[0]), "r"(b[1]));
}
__device__ __forceinline__ void cp_async16(uint32_t dst, const void* src) {
    asm volatile("cp.async.cg.shared.global [%0], [%1], 16;"
                 :: "r"(dst), "l"(__cvta_generic_to_global(src)) : "memory");
}
#define CP_COMMIT() asm volatile("cp.async.commit_group;" ::: "memory")

// ===========================================================================
// 0) W transpose + hi/lo bf16 split
// ===========================================================================
__global__ __launch_bounds__(256) void conv_w_kernel(const float* __restrict__ W) {
    int idx = blockIdx.x * 256 + threadIdx.x;
    if (idx >= D_IN * D_OUT) return;
    int k = idx / D_OUT, n = idx % D_OUT;
    float v = W[idx];
    __nv_bfloat16 h = __float2bfloat16_rn(v);
    __nv_bfloat16 l = __float2bfloat16_rn(v - __bfloat162float(h));
    g_Wth[(size_t)n * D_IN + k] = h;
    g_Wtl[(size_t)n * D_IN + k] = l;
}

// ===========================================================================
// 1) GEMM: pre_sup = x @ W via mma.sync bf16 hi/lo, 2-stage cp.async pipeline
// ===========================================================================
#define BM 128
#define BN 128
#define BK 32
#define NKC (D_IN / BK)     // 16 chunks
#define ROW_B 80
#define ST_A_HI 0
#define ST_A_LO 10240
#define ST_B_HI 20480
#define ST_B_LO 30720
#define STAGE_B 40960
#define SM_TOTAL (2 * STAGE_B)   // 81920

__global__ __launch_bounds__(256, 1) void gemm_tc_kernel(const float* __restrict__ x) {
    extern __shared__ __align__(16) char smem[];
    const uint32_t sbase = smem_u32(smem);

    const int tid = threadIdx.x;
    const int wid = tid >> 5;
    const int lane = tid & 31;
    const int n0 = blockIdx.x * BN;    // grid.x = 2: both N-blocks of an m-tile adjacent
    const int m0 = blockIdx.y * BM;
    const int warp_m = (wid & 1) * 64;
    const int warp_n = (wid >> 1) * 32;

    const int a_row = tid >> 3;
    const int a_f4  = tid & 7;
    float4 areg[4];

    float acc[4][4][4];
#pragma unroll
    for (int i = 0; i < 4; i++)
#pragma unroll
        for (int j = 0; j < 4; j++)
#pragma unroll
            for (int t = 0; t < 4; t++) acc[i][j][t] = 0.f;

    const uint32_t aLane = (uint32_t)((warp_m + (lane & 15)) * ROW_B + ((lane >> 4) << 4));
    const uint32_t bLane = (uint32_t)((warp_n + (lane & 7)) * ROW_B + ((lane >> 3) << 4));

    auto ldgA = [&](int kc) {
        const int k0 = kc * BK;
#pragma unroll
        for (int i = 0; i < 4; i++) {
            int row = a_row + i * 32;
            int m = m0 + row;
            areg[i] = make_float4(0.f, 0.f, 0.f, 0.f);
            if (m < N_NODES)
                areg[i] = *(const float4*)(x + (size_t)m * D_IN + k0 + a_f4 * 4);
        }
    };
    auto stsA = [&](int st) {
        char* sb = smem + st * STAGE_B;
#pragma unroll
        for (int i = 0; i < 4; i++) {
            float4 a = areg[i];
            int row = a_row + i * 32;
            __nv_bfloat16 h0 = __float2bfloat16_rn(a.x), h1 = __float2bfloat16_rn(a.y);
            __nv_bfloat16 h2 = __float2bfloat16_rn(a.z), h3 = __float2bfloat16_rn(a.w);
            __nv_bfloat16 l0 = __float2bfloat16_rn(a.x - __bfloat162float(h0));
            __nv_bfloat16 l1 = __float2bfloat16_rn(a.y - __bfloat162float(h1));
            __nv_bfloat16 l2 = __float2bfloat16_rn(a.z - __bfloat162float(h2));
            __nv_bfloat16 l3 = __float2bfloat16_rn(a.w - __bfloat162float(h3));
            int off = row * ROW_B + a_f4 * 8;
            *(uint2*)(sb + ST_A_HI + off) = make_uint2(pack_bf2(h0, h1), pack_bf2(h2, h3));
            *(uint2*)(sb + ST_A_LO + off) = make_uint2(pack_bf2(l0, l1), pack_bf2(l2, l3));
        }
    };
    auto cpB = [&](int kc, int st) {
        const int k0 = kc * BK;
        const uint32_t stb = sbase + st * STAGE_B;
#pragma unroll
        for (int i = 0; i < 4; i++) {
            int idx = tid + i * 256;
            int sub = idx & 511;
            int row = sub >> 2;
            int ch  = sub & 3;
            uint32_t off = (uint32_t)(row * ROW_B + ch * 16);
            if (idx < 512)
                cp_async16(stb + ST_B_HI + off, g_Wth + (size_t)(n0 + row) * D_IN + k0 + ch * 8);
            else
                cp_async16(stb + ST_B_LO + off, g_Wtl + (size_t)(n0 + row) * D_IN + k0 + ch * 8);
        }
        CP_COMMIT();
    };

    // ---- prologue
    ldgA(0);
    cpB(0, 0);
    stsA(0);
    ldgA(1);
    cpB(1, 1);
    asm volatile("cp.async.wait_group 1;" ::: "memory");
    __syncthreads();

    for (int kc = 0; kc < NKC; kc++) {
        const int cur = kc & 1;
        const uint32_t base = sbase + cur * STAGE_B;

        uint32_t bh[4][4], bl[4][4];
#pragma unroll
        for (int nt = 0; nt < 4; nt++) {
            ldmatrix_x4(bh[nt], base + ST_B_HI + bLane + nt * 8 * ROW_B);
            ldmatrix_x4(bl[nt], base + ST_B_LO + bLane + nt * 8 * ROW_B);
        }
#pragma unroll
        for (int ks = 0; ks < 2; ks++) {
            uint32_t ah[4][4], al[4][4];
#pragma unroll
            for (int mt = 0; mt < 4; mt++) {
                ldmatrix_x4(ah[mt], base + ST_A_HI + aLane + mt * 16 * ROW_B + ks * 32);
                ldmatrix_x4(al[mt], base + ST_A_LO + aLane + mt * 16 * ROW_B + ks * 32);
            }
#pragma unroll
            for (int mt = 0; mt < 4; mt++) {
#pragma unroll
                for (int nt = 0; nt < 4; nt++) {
                    uint32_t bhp[2] = {bh[nt][ks * 2], bh[nt][ks * 2 + 1]};
                    uint32_t blp[2] = {bl[nt][ks * 2], bl[nt][ks * 2 + 1]};
                    mma_bf16(acc[mt][nt], ah[mt], bhp);
                    mma_bf16(acc[mt][nt], ah[mt], blp);
                    mma_bf16(acc[mt][nt], al[mt], bhp);
                }
            }
        }

        if (kc < NKC - 1) stsA(cur ^ 1);
        __syncthreads();
        if (kc < NKC - 2) {
            ldgA(kc + 2);
            cpB(kc + 2, cur);
        }
        if (kc < NKC - 1) {
            if (kc < NKC - 2)
                asm volatile("cp.async.wait_group 1;" ::: "memory");
            else
                asm volatile("cp.async.wait_group 0;" ::: "memory");
            __syncthreads();
        }
    }

    // ---- epilogue
    const int mrow = m0 + warp_m + (lane >> 2);
    const int ncol = n0 + warp_n + (lane & 3) * 2;
#pragma unroll
    for (int mt = 0; mt < 4; mt++) {
#pragma unroll
        for (int nt = 0; nt < 4; nt++) {
            int m = mrow + mt * 16;
            int n = ncol + nt * 8;
            if (m < N_NODES)
                *(float2*)(g_presup + (size_t)m * D_OUT + n) =
                    make_float2(acc[mt][nt][0], acc[mt][nt][1]);
            if (m + 8 < N_NODES)
                *(float2*)(g_presup + (size_t)(m + 8) * D_OUT + n) =
                    make_float2(acc[mt][nt][2], acc[mt][nt][3]);
        }
    }
}

// ===========================================================================
// 2a) CSR binning: count -> scan -> scatter
// ===========================================================================
__global__ __launch_bounds__(1024) void zero_counts_kernel() {
    int i = blockIdx.x * 1024 + threadIdx.x;
    if (i < N_NODES) g_counts[i] = 0;
}

__global__ __launch_bounds__(256) void count_kernel(const int* __restrict__ erow) {
    int e = blockIdx.x * 256 + threadIdx.x;
    if (e < N_EDGES) atomicAdd(&g_counts[__ldg(erow + e)], 1);
}

__global__ __launch_bounds__(1024) void scan1_kernel() {
    const int tid = threadIdx.x, lane = tid & 31, wid = tid >> 5;
    const int i = blockIdx.x * 1024 + tid;
    int v = (i < N_NODES) ? g_counts[i] : 0;
    int inc = v;
#pragma unroll
    for (int d = 1; d < 32; d <<= 1) {
        int t = __shfl_up_sync(~0u, inc, d);
        if (lane >= d) inc += t;
    }
    __shared__ int ws[32];
    if (lane == 31) ws[wid] = inc;
    __syncthreads();
    if (wid == 0) {
        int w = ws[lane];
#pragma unroll
        for (int d = 1; d < 32; d <<= 1) {
            int t = __shfl_up_sync(~0u, w, d);
            if (lane >= d) w += t;
        }
        ws[lane] = w;
    }
    __syncthreads();
    int base = wid ? ws[wid - 1] : 0;
    if (i < N_NODES) g_rowptr[i] = base + inc - v;
    if (tid == 0) g_blocksums[blockIdx.x] = ws[31];
}

__global__ __launch_bounds__(128) void scan2_kernel() {
    __shared__ int s[128];
    const int tid = threadIdx.x;
    s[tid] = (tid < NB1) ? g_blocksums[tid] : 0;
    __syncthreads();
    for (int d = 1; d < 128; d <<= 1) {
        int t = (tid >= d) ? s[tid - d] : 0;
        __syncthreads();
        s[tid] += t;
        __syncthreads();
    }
    g_blocksums[tid] = (tid > 0) ? s[tid - 1] : 0;
}

__global__ __launch_bounds__(1024) void scan3_kernel() {
    int i = blockIdx.x * 1024 + threadIdx.x;
    if (i < N_NODES) {
        int rp = g_rowptr[i] + g_blocksums[blockIdx.x];
        g_rowptr[i] = rp;
        g_cursor[i] = rp;
    }
    if (i == 0) g_rowptr[N_NODES] = N_EDGES;
}

__global__ __launch_bounds__(256) void scatter_kernel(const int* __restrict__ erow,
                                                      const int* __restrict__ ecol,
                                                      const float* __restrict__ evals) {
    int e = blockIdx.x * 256 + threadIdx.x;
    if (e >= N_EDGES) return;
    int r = __ldg(erow + e);
    int p = atomicAdd(&g_cursor[r], 1);
    g_csr_pair[p] = make_int2(__ldg(ecol + e), __float_as_int(__ldg(evals + e)));
}

// ===========================================================================
// 2b) SpMM CSR: one warp per row, unroll x4 for gather MLP, streaming hints
// ===========================================================================
__global__ __launch_bounds__(256) void spmm_csr_kernel(float* __restrict__ out) {
    const int lane = threadIdx.x & 31;
    const int r = (blockIdx.x * 256 + threadIdx.x) >> 5;
    if (r >= N_NODES) return;
    const int beg = __ldg(g_rowptr + r);
    const int end = __ldg(g_rowptr + r + 1);

    float4 A0 = make_float4(0.f, 0.f, 0.f, 0.f);
    float4 A1 = make_float4(0.f, 0.f, 0.f, 0.f);
    const float4* base = (const float4*)g_presup;
    const int lo = lane * 2;

    int e = beg;
    for (; e + 4 <= end; e += 4) {
        int2 pr0 = __ldcs(g_csr_pair + e);
        int2 pr1 = __ldcs(g_csr_pair + e + 1);
        int2 pr2 = __ldcs(g_csr_pair + e + 2);
        int2 pr3 = __ldcs(g_csr_pair + e + 3);
        const float4* s0 = base + (size_t)pr0.x * (D_OUT / 4) + lo;
        const float4* s1 = base + (size_t)pr1.x * (D_OUT / 4) + lo;
        const float4* s2 = base + (size_t)pr2.x * (D_OUT / 4) + lo;
        const float4* s3 = base + (size_t)pr3.x * (D_OUT / 4) + lo;
        float4 p00 = __ldg(s0), p01 = __ldg(s0 + 1);
        float4 p10 = __ldg(s1), p11 = __ldg(s1 + 1);
        float4 p20 = __ldg(s2), p21 = __ldg(s2 + 1);
        float4 p30 = __ldg(s3), p31 = __ldg(s3 + 1);
        float v0 = __int_as_float(pr0.y);
        float v1 = __int_as_float(pr1.y);
        float v2 = __int_as_float(pr2.y);
        float v3 = __int_as_float(pr3.y);
        A0.x = fmaf(v0, p00.x, A0.x); A0.y = fmaf(v0, p00.y, A0.y);
        A0.z = fmaf(v0, p00.z, A0.z); A0.w = fmaf(v0, p00.w, A0.w);
        A1.x = fmaf(v0, p01.x, A1.x); A1.y = fmaf(v0, p01.y, A1.y);
        A1.z = fmaf(v0, p01.z, A1.z); A1.w = fmaf(v0, p01.w, A1.w);
        A0.x = fmaf(v1, p10.x, A0.x); A0.y = fmaf(v1, p10.y, A0.y);
        A0.z = fmaf(v1, p10.z, A0.z); A0.w = fmaf(v1, p10.w, A0.w);
        A1.x = fmaf(v1, p11.x, A1.x); A1.y = fmaf(v1, p11.y, A1.y);
        A1.z = fmaf(v1, p11.z, A1.z); A1.w = fmaf(v1, p11.w, A1.w);
        A0.x = fmaf(v2, p20.x, A0.x); A0.y = fmaf(v2, p20.y, A0.y);
        A0.z = fmaf(v2, p20.z, A0.z); A0.w = fmaf(v2, p20.w, A0.w);
        A1.x = fmaf(v2, p21.x, A1.x); A1.y = fmaf(v2, p21.y, A1.y);
        A1.z = fmaf(v2, p21.z, A1.z); A1.w = fmaf(v2, p21.w, A1.w);
        A0.x = fmaf(v3, p30.x, A0.x); A0.y = fmaf(v3, p30.y, A0.y);
        A0.z = fmaf(v3, p30.z, A0.z); A0.w = fmaf(v3, p30.w, A0.w);
        A1.x = fmaf(v3, p31.x, A1.x); A1.y = fmaf(v3, p31.y, A1.y);
        A1.z = fmaf(v3, p31.z, A1.z); A1.w = fmaf(v3, p31.w, A1.w);
    }
    for (; e < end; e++) {
        int2 pr0 = __ldcs(g_csr_pair + e);
        float v0 = __int_as_float(pr0.y);
        const float4* s0 = base + (size_t)pr0.x * (D_OUT / 4) + lo;
        float4 p00 = __ldg(s0), p01 = __ldg(s0 + 1);
        A0.x = fmaf(v0, p00.x, A0.x); A0.y = fmaf(v0, p00.y, A0.y);
        A0.z = fmaf(v0, p00.z, A0.z); A0.w = fmaf(v0, p00.w, A0.w);
        A1.x = fmaf(v0, p01.x, A1.x); A1.y = fmaf(v0, p01.y, A1.y);
        A1.z = fmaf(v0, p01.z, A1.z); A1.w = fmaf(v0, p01.w, A1.w);
    }

    float4* dst = (float4*)(out + (size_t)r * D_OUT) + lo;
    __stcs(dst, A0);
    __stcs(dst + 1, A1);
}

// ===========================================================================
// 3) Column sum-of-squares of (agg + b)
// ===========================================================================
#define ROWS_PER_BLOCK 256
__global__ __launch_bounds__(256) void colsumsq_kernel(const float* __restrict__ out,
                                                       const float* __restrict__ b) {
    const int c = threadIdx.x;
    const float bias = __ldg(b + c);
    const int r0 = blockIdx.x * ROWS_PER_BLOCK;
    const int r1 = min(r0 + ROWS_PER_BLOCK, N_NODES);
    float s = 0.f;
    for (int r = r0; r < r1; r++) {
        float v = out[(size_t)r * D_OUT + c] + bias;
        s = fmaf(v, v, s);
    }
    atomicAdd(&g_colsum[c], s);
}

__global__ void zero_colsum_kernel() { g_colsum[threadIdx.x] = 0.f; }

// ===========================================================================
// 4) Finalize: out = softplus((agg + b) / max(col_norm, 1e-12))
// ===========================================================================
__global__ __launch_bounds__(256) void finalize_kernel(float* __restrict__ out,
                                                       const float* __restrict__ b) {
    const int c = threadIdx.x;
    const float bias = __ldg(b + c);
    const float inv = 1.f / fmaxf(sqrtf(g_colsum[c]), 1e-12f);
    for (int r = blockIdx.x; r < N_NODES; r += gridDim.x) {
        float v = (out[(size_t)r * D_OUT + c] + bias) * inv;
        out[(size_t)r * D_OUT + c] = fmaxf(v, 0.f) + log1pf(__expf(-fabsf(v)));
    }
}

// ===========================================================================
extern "C" void kernel_launch(void* const* d_in, const int* in_sizes, int n_in,
                              void* d_out, int out_size) {
    const float* x     = (const float*)d_in[0];
    const int*   erow  = (const int*)  d_in[1];
    const int*   ecol  = (const int*)  d_in[2];
    const float* evals = (const float*)d_in[3];
    const float* W     = (const float*)d_in[4];
    const float* b     = (const float*)d_in[5];
    float* out = (float*)d_out;

    cudaFuncSetAttribute(gemm_tc_kernel,
                         cudaFuncAttributeMaxDynamicSharedMemorySize, SM_TOTAL);

    zero_colsum_kernel<<<1, D_OUT>>>();
    conv_w_kernel<<<(D_IN * D_OUT + 255) / 256, 256>>>(W);

    // CSR binning (independent of GEMM)
    zero_counts_kernel<<<NB1, 1024>>>();
    count_kernel<<<(N_EDGES + 255) / 256, 256>>>(erow);
    scan1_kernel<<<NB1, 1024>>>();
    scan2_kernel<<<1, 128>>>();
    scan3_kernel<<<NB1, 1024>>>();
    scatter_kernel<<<(N_EDGES + 255) / 256, 256>>>(erow, ecol, evals);

    // GEMM (grid.x = N-blocks so both share the m-tile in L2)
    dim3 ggrid(D_OUT / BN, (N_NODES + BM - 1) / BM);
    gemm_tc_kernel<<<ggrid, 256, SM_TOTAL>>>(x);

    // SpMM (CSR, no atomics, one warp per row)
    spmm_csr_kernel<<<(N_NODES * 32 + 255) / 256, 256>>>(out);

    colsumsq_kernel<<<(N_NODES + ROWS_PER_BLOCK - 1) / ROWS_PER_BLOCK, 256>>>(out, b);
    finalize_kernel<<<4096, 256>>>(out, b);
}

// round 9
// speedup vs baseline: 1.2549x; 1.0569x over previous
#include <cuda_runtime.h>
#include <cuda_bf16.h>
#include <cstdint>
#include <math.h>

#define N_NODES 100000
#define N_EDGES 3200000
#define D_IN    512
#define D_OUT   256
#define NB1     ((N_NODES + 1023) / 1024)   // 98 scan blocks

// Scratch (no cudaMalloc allowed)
__device__ __align__(16) float g_presup[(size_t)N_NODES * D_OUT];   // 102.4 MB
__device__ float g_colsum[D_OUT];
__device__ __align__(16) __nv_bfloat16 g_Wth[(size_t)D_OUT * D_IN]; // W^T hi [n][k]
__device__ __align__(16) __nv_bfloat16 g_Wtl[(size_t)D_OUT * D_IN]; // W^T lo [n][k]
// CSR binning scratch
__device__ int   g_counts[N_NODES];
__device__ int   g_rowptr[N_NODES + 1];
__device__ int   g_cursor[N_NODES];
__device__ int   g_blocksums[128];
__device__ __align__(16) int2 g_csr_pair[N_EDGES];   // (col, val bits)

__device__ __forceinline__ uint32_t smem_u32(const void* p) {
    uint32_t a;
    asm("{ .reg .u64 t; cvta.to.shared.u64 t, %1; cvt.u32.u64 %0, t; }" : "=r"(a) : "l"(p));
    return a;
}
__device__ __forceinline__ uint32_t pack_bf2(__nv_bfloat16 a, __nv_bfloat16 b) {
    __nv_bfloat162 t = __halves2bfloat162(a, b);
    return *reinterpret_cast<uint32_t*>(&t);
}
__device__ __forceinline__ void ldmatrix_x4(uint32_t* r, uint32_t addr) {
    asm volatile("ldmatrix.sync.aligned.m8n8.x4.shared.b16 {%0,%1,%2,%3}, [%4];"
                 : "=r"(r[0]), "=r"(r[1]), "=r"(r[2]), "=r"(r[3]) : "r"(addr));
}
__device__ __forceinline__ void mma_bf16(float* d, const uint32_t* a, const uint32_t* b) {
    asm volatile(
        "mma.sync.aligned.m16n8k16.row.col.f32.bf16.bf16.f32 "
        "{%0,%1,%2,%3}, {%4,%5,%6,%7}, {%8,%9}, {%0,%1,%2,%3};"
        : "+f"(d[0]), "+f"(d[1]), "+f"(d[2]), "+f"(d[3])
        : "r"(a[0]), "r"(a[1]), "r"(a[2]), "r"(a[3]), "r"(b[0]), "r"(b[1]));
}
__device__ __forceinline__ void cp_async16(uint32_t dst, const void* src) {
    asm volatile("cp.async.cg.shared.global [%0], [%1], 16;"
                 :: "r"(dst), "l"(__cvta_generic_to_global(src)) : "memory");
}
#define CP_COMMIT() asm volatile("cp.async.commit_group;" ::: "memory")

// ===========================================================================
// 0) W transpose + hi/lo bf16 split
// ===========================================================================
__global__ __launch_bounds__(256) void conv_w_kernel(const float* __restrict__ W) {
    int idx = blockIdx.x * 256 + threadIdx.x;
    if (idx >= D_IN * D_OUT) return;
    int k = idx / D_OUT, n = idx % D_OUT;
    float v = W[idx];
    __nv_bfloat16 h = __float2bfloat16_rn(v);
    __nv_bfloat16 l = __float2bfloat16_rn(v - __bfloat162float(h));
    g_Wth[(size_t)n * D_IN + k] = h;
    g_Wtl[(size_t)n * D_IN + k] = l;
}

// ===========================================================================
// 1) GEMM: pre_sup = x @ W via mma.sync bf16 hi/lo, 2-stage cp.async pipeline
// ===========================================================================
#define BM 128
#define BN 128
#define BK 32
#define NKC (D_IN / BK)     // 16 chunks
#define ROW_B 80
#define ST_A_HI 0
#define ST_A_LO 10240
#define ST_B_HI 20480
#define ST_B_LO 30720
#define STAGE_B 40960
#define SM_TOTAL (2 * STAGE_B)   // 81920

__global__ __launch_bounds__(256, 1) void gemm_tc_kernel(const float* __restrict__ x) {
    extern __shared__ __align__(16) char smem[];
    const uint32_t sbase = smem_u32(smem);

    const int tid = threadIdx.x;
    const int wid = tid >> 5;
    const int lane = tid & 31;
    const int n0 = blockIdx.x * BN;    // grid.x = 2: both N-blocks of an m-tile adjacent
    const int m0 = blockIdx.y * BM;
    const int warp_m = (wid & 1) * 64;
    const int warp_n = (wid >> 1) * 32;

    const int a_row = tid >> 3;
    const int a_f4  = tid & 7;
    float4 areg[4];

    float acc[4][4][4];
#pragma unroll
    for (int i = 0; i < 4; i++)
#pragma unroll
        for (int j = 0; j < 4; j++)
#pragma unroll
            for (int t = 0; t < 4; t++) acc[i][j][t] = 0.f;

    const uint32_t aLane = (uint32_t)((warp_m + (lane & 15)) * ROW_B + ((lane >> 4) << 4));
    const uint32_t bLane = (uint32_t)((warp_n + (lane & 7)) * ROW_B + ((lane >> 3) << 4));

    auto ldgA = [&](int kc) {
        const int k0 = kc * BK;
#pragma unroll
        for (int i = 0; i < 4; i++) {
            int row = a_row + i * 32;
            int m = m0 + row;
            areg[i] = make_float4(0.f, 0.f, 0.f, 0.f);
            if (m < N_NODES)
                areg[i] = *(const float4*)(x + (size_t)m * D_IN + k0 + a_f4 * 4);
        }
    };
    auto stsA = [&](int st) {
        char* sb = smem + st * STAGE_B;
#pragma unroll
        for (int i = 0; i < 4; i++) {
            float4 a = areg[i];
            int row = a_row + i * 32;
            __nv_bfloat16 h0 = __float2bfloat16_rn(a.x), h1 = __float2bfloat16_rn(a.y);
            __nv_bfloat16 h2 = __float2bfloat16_rn(a.z), h3 = __float2bfloat16_rn(a.w);
            __nv_bfloat16 l0 = __float2bfloat16_rn(a.x - __bfloat162float(h0));
            __nv_bfloat16 l1 = __float2bfloat16_rn(a.y - __bfloat162float(h1));
            __nv_bfloat16 l2 = __float2bfloat16_rn(a.z - __bfloat162float(h2));
            __nv_bfloat16 l3 = __float2bfloat16_rn(a.w - __bfloat162float(h3));
            int off = row * ROW_B + a_f4 * 8;
            *(uint2*)(sb + ST_A_HI + off) = make_uint2(pack_bf2(h0, h1), pack_bf2(h2, h3));
            *(uint2*)(sb + ST_A_LO + off) = make_uint2(pack_bf2(l0, l1), pack_bf2(l2, l3));
        }
    };
    auto cpB = [&](int kc, int st) {
        const int k0 = kc * BK;
        const uint32_t stb = sbase + st * STAGE_B;
#pragma unroll
        for (int i = 0; i < 4; i++) {
            int idx = tid + i * 256;
            int sub = idx & 511;
            int row = sub >> 2;
            int ch  = sub & 3;
            uint32_t off = (uint32_t)(row * ROW_B + ch * 16);
            if (idx < 512)
                cp_async16(stb + ST_B_HI + off, g_Wth + (size_t)(n0 + row) * D_IN + k0 + ch * 8);
            else
                cp_async16(stb + ST_B_LO + off, g_Wtl + (size_t)(n0 + row) * D_IN + k0 + ch * 8);
        }
        CP_COMMIT();
    };

    // ---- prologue
    ldgA(0);
    cpB(0, 0);
    stsA(0);
    ldgA(1);
    cpB(1, 1);
    asm volatile("cp.async.wait_group 1;" ::: "memory");
    __syncthreads();

    for (int kc = 0; kc < NKC; kc++) {
        const int cur = kc & 1;
        const uint32_t base = sbase + cur * STAGE_B;

        uint32_t bh[4][4], bl[4][4];
#pragma unroll
        for (int nt = 0; nt < 4; nt++) {
            ldmatrix_x4(bh[nt], base + ST_B_HI + bLane + nt * 8 * ROW_B);
            ldmatrix_x4(bl[nt], base + ST_B_LO + bLane + nt * 8 * ROW_B);
        }
#pragma unroll
        for (int ks = 0; ks < 2; ks++) {
            uint32_t ah[4][4], al[4][4];
#pragma unroll
            for (int mt = 0; mt < 4; mt++) {
                ldmatrix_x4(ah[mt], base + ST_A_HI + aLane + mt * 16 * ROW_B + ks * 32);
                ldmatrix_x4(al[mt], base + ST_A_LO + aLane + mt * 16 * ROW_B + ks * 32);
            }
#pragma unroll
            for (int mt = 0; mt < 4; mt++) {
#pragma unroll
                for (int nt = 0; nt < 4; nt++) {
                    uint32_t bhp[2] = {bh[nt][ks * 2], bh[nt][ks * 2 + 1]};
                    uint32_t blp[2] = {bl[nt][ks * 2], bl[nt][ks * 2 + 1]};
                    mma_bf16(acc[mt][nt], ah[mt], bhp);
                    mma_bf16(acc[mt][nt], ah[mt], blp);
                    mma_bf16(acc[mt][nt], al[mt], bhp);
                }
            }
        }

        if (kc < NKC - 1) stsA(cur ^ 1);
        __syncthreads();
        if (kc < NKC - 2) {
            ldgA(kc + 2);
            cpB(kc + 2, cur);
        }
        if (kc < NKC - 1) {
            if (kc < NKC - 2)
                asm volatile("cp.async.wait_group 1;" ::: "memory");
            else
                asm volatile("cp.async.wait_group 0;" ::: "memory");
            __syncthreads();
        }
    }

    // ---- epilogue
    const int mrow = m0 + warp_m + (lane >> 2);
    const int ncol = n0 + warp_n + (lane & 3) * 2;
#pragma unroll
    for (int mt = 0; mt < 4; mt++) {
#pragma unroll
        for (int nt = 0; nt < 4; nt++) {
            int m = mrow + mt * 16;
            int n = ncol + nt * 8;
            if (m < N_NODES)
                *(float2*)(g_presup + (size_t)m * D_OUT + n) =
                    make_float2(acc[mt][nt][0], acc[mt][nt][1]);
            if (m + 8 < N_NODES)
                *(float2*)(g_presup + (size_t)(m + 8) * D_OUT + n) =
                    make_float2(acc[mt][nt][2], acc[mt][nt][3]);
        }
    }
}

// ===========================================================================
// 2a) CSR binning: count -> scan -> scatter
// ===========================================================================
__global__ __launch_bounds__(1024) void zero_counts_kernel() {
    int i = blockIdx.x * 1024 + threadIdx.x;
    if (i < N_NODES) g_counts[i] = 0;
}

__global__ __launch_bounds__(256) void count_kernel(const int* __restrict__ erow) {
    int e = blockIdx.x * 256 + threadIdx.x;
    if (e < N_EDGES) atomicAdd(&g_counts[__ldg(erow + e)], 1);
}

__global__ __launch_bounds__(1024) void scan1_kernel() {
    const int tid = threadIdx.x, lane = tid & 31, wid = tid >> 5;
    const int i = blockIdx.x * 1024 + tid;
    int v = (i < N_NODES) ? g_counts[i] : 0;
    int inc = v;
#pragma unroll
    for (int d = 1; d < 32; d <<= 1) {
        int t = __shfl_up_sync(~0u, inc, d);
        if (lane >= d) inc += t;
    }
    __shared__ int ws[32];
    if (lane == 31) ws[wid] = inc;
    __syncthreads();
    if (wid == 0) {
        int w = ws[lane];
#pragma unroll
        for (int d = 1; d < 32; d <<= 1) {
            int t = __shfl_up_sync(~0u, w, d);
            if (lane >= d) w += t;
        }
        ws[lane] = w;
    }
    __syncthreads();
    int base = wid ? ws[wid - 1] : 0;
    if (i < N_NODES) g_rowptr[i] = base + inc - v;
    if (tid == 0) g_blocksums[blockIdx.x] = ws[31];
}

__global__ __launch_bounds__(128) void scan2_kernel() {
    __shared__ int s[128];
    const int tid = threadIdx.x;
    s[tid] = (tid < NB1) ? g_blocksums[tid] : 0;
    __syncthreads();
    for (int d = 1; d < 128; d <<= 1) {
        int t = (tid >= d) ? s[tid - d] : 0;
        __syncthreads();
        s[tid] += t;
        __syncthreads();
    }
    g_blocksums[tid] = (tid > 0) ? s[tid - 1] : 0;
}

__global__ __launch_bounds__(1024) void scan3_kernel() {
    int i = blockIdx.x * 1024 + threadIdx.x;
    if (i < N_NODES) {
        int rp = g_rowptr[i] + g_blocksums[blockIdx.x];
        g_rowptr[i] = rp;
        g_cursor[i] = rp;
    }
    if (i == 0) g_rowptr[N_NODES] = N_EDGES;
}

__global__ __launch_bounds__(256) void scatter_kernel(const int* __restrict__ erow,
                                                      const int* __restrict__ ecol,
                                                      const float* __restrict__ evals) {
    int e = blockIdx.x * 256 + threadIdx.x;
    if (e >= N_EDGES) return;
    int r = __ldg(erow + e);
    int p = atomicAdd(&g_cursor[r], 1);
    g_csr_pair[p] = make_int2(__ldg(ecol + e), __float_as_int(__ldg(evals + e)));
}

// ===========================================================================
// 2b) SpMM CSR: one warp per row (round-5 exact: x2 unroll, __ldg, plain st)
// ===========================================================================
__global__ __launch_bounds__(256) void spmm_csr_kernel(float* __restrict__ out) {
    const int lane = threadIdx.x & 31;
    const int r = (blockIdx.x * 256 + threadIdx.x) >> 5;
    if (r >= N_NODES) return;
    const int beg = __ldg(g_rowptr + r);
    const int end = __ldg(g_rowptr + r + 1);

    float4 A0 = make_float4(0.f, 0.f, 0.f, 0.f);
    float4 A1 = make_float4(0.f, 0.f, 0.f, 0.f);
    const float4* base = (const float4*)g_presup;
    const int lo = lane * 2;

    int e = beg;
    for (; e + 2 <= end; e += 2) {
        int2 pr0 = __ldg(g_csr_pair + e);
        int2 pr1 = __ldg(g_csr_pair + e + 1);
        float v0 = __int_as_float(pr0.y);
        float v1 = __int_as_float(pr1.y);
        const float4* s0 = base + (size_t)pr0.x * (D_OUT / 4) + lo;
        const float4* s1 = base + (size_t)pr1.x * (D_OUT / 4) + lo;
        float4 p00 = __ldg(s0), p01 = __ldg(s0 + 1);
        float4 p10 = __ldg(s1), p11 = __ldg(s1 + 1);
        A0.x = fmaf(v0, p00.x, A0.x); A0.y = fmaf(v0, p00.y, A0.y);
        A0.z = fmaf(v0, p00.z, A0.z); A0.w = fmaf(v0, p00.w, A0.w);
        A1.x = fmaf(v0, p01.x, A1.x); A1.y = fmaf(v0, p01.y, A1.y);
        A1.z = fmaf(v0, p01.z, A1.z); A1.w = fmaf(v0, p01.w, A1.w);
        A0.x = fmaf(v1, p10.x, A0.x); A0.y = fmaf(v1, p10.y, A0.y);
        A0.z = fmaf(v1, p10.z, A0.z); A0.w = fmaf(v1, p10.w, A0.w);
        A1.x = fmaf(v1, p11.x, A1.x); A1.y = fmaf(v1, p11.y, A1.y);
        A1.z = fmaf(v1, p11.z, A1.z); A1.w = fmaf(v1, p11.w, A1.w);
    }
    if (e < end) {
        int2 pr0 = __ldg(g_csr_pair + e);
        float v0 = __int_as_float(pr0.y);
        const float4* s0 = base + (size_t)pr0.x * (D_OUT / 4) + lo;
        float4 p00 = __ldg(s0), p01 = __ldg(s0 + 1);
        A0.x = fmaf(v0, p00.x, A0.x); A0.y = fmaf(v0, p00.y, A0.y);
        A0.z = fmaf(v0, p00.z, A0.z); A0.w = fmaf(v0, p00.w, A0.w);
        A1.x = fmaf(v0, p01.x, A1.x); A1.y = fmaf(v0, p01.y, A1.y);
        A1.z = fmaf(v0, p01.z, A1.z); A1.w = fmaf(v0, p01.w, A1.w);
    }

    float4* dst = (float4*)(out + (size_t)r * D_OUT) + lo;
    dst[0] = A0;
    dst[1] = A1;
}

// ===========================================================================
// 3) Column sum-of-squares of (agg + b)
// ===========================================================================
#define ROWS_PER_BLOCK 256
__global__ __launch_bounds__(256) void colsumsq_kernel(const float* __restrict__ out,
                                                       const float* __restrict__ b) {
    const int c = threadIdx.x;
    const float bias = __ldg(b + c);
    const int r0 = blockIdx.x * ROWS_PER_BLOCK;
    const int r1 = min(r0 + ROWS_PER_BLOCK, N_NODES);
    float s = 0.f;
    for (int r = r0; r < r1; r++) {
        float v = out[(size_t)r * D_OUT + c] + bias;
        s = fmaf(v, v, s);
    }
    atomicAdd(&g_colsum[c], s);
}

__global__ void zero_colsum_kernel() { g_colsum[threadIdx.x] = 0.f; }

// ===========================================================================
// 4) Finalize: out = softplus((agg + b) / max(col_norm, 1e-12))
// ===========================================================================
__global__ __launch_bounds__(256) void finalize_kernel(float* __restrict__ out,
                                                       const float* __restrict__ b) {
    const int c = threadIdx.x;
    const float bias = __ldg(b + c);
    const float inv = 1.f / fmaxf(sqrtf(g_colsum[c]), 1e-12f);
    for (int r = blockIdx.x; r < N_NODES; r += gridDim.x) {
        float v = (out[(size_t)r * D_OUT + c] + bias) * inv;
        out[(size_t)r * D_OUT + c] = fmaxf(v, 0.f) + log1pf(__expf(-fabsf(v)));
    }
}

// ===========================================================================
extern "C" void kernel_launch(void* const* d_in, const int* in_sizes, int n_in,
                              void* d_out, int out_size) {
    const float* x     = (const float*)d_in[0];
    const int*   erow  = (const int*)  d_in[1];
    const int*   ecol  = (const int*)  d_in[2];
    const float* evals = (const float*)d_in[3];
    const float* W     = (const float*)d_in[4];
    const float* b     = (const float*)d_in[5];
    float* out = (float*)d_out;

    static cudaStream_t s2 = nullptr;
    static cudaEvent_t evFork = nullptr, evJoin = nullptr;
    if (!s2) {
        cudaStreamCreateWithFlags(&s2, cudaStreamNonBlocking);
        cudaEventCreateWithFlags(&evFork, cudaEventDisableTiming);
        cudaEventCreateWithFlags(&evJoin, cudaEventDisableTiming);
        cudaFuncSetAttribute(gemm_tc_kernel,
                             cudaFuncAttributeMaxDynamicSharedMemorySize, SM_TOTAL);
    }

    // ---- fork: binning chain on s2, GEMM path on main stream (0)
    cudaEventRecord(evFork, 0);
    cudaStreamWaitEvent(s2, evFork, 0);

    // s2: CSR binning (independent of W/x path)
    zero_counts_kernel<<<NB1, 1024, 0, s2>>>();
    count_kernel<<<(N_EDGES + 255) / 256, 256, 0, s2>>>(erow);
    scan1_kernel<<<NB1, 1024, 0, s2>>>();
    scan2_kernel<<<1, 128, 0, s2>>>();
    scan3_kernel<<<NB1, 1024, 0, s2>>>();
    scatter_kernel<<<(N_EDGES + 255) / 256, 256, 0, s2>>>(erow, ecol, evals);
    cudaEventRecord(evJoin, s2);

    // main: W conversion + GEMM
    zero_colsum_kernel<<<1, D_OUT>>>();
    conv_w_kernel<<<(D_IN * D_OUT + 255) / 256, 256>>>(W);
    dim3 ggrid(D_OUT / BN, (N_NODES + BM - 1) / BM);
    gemm_tc_kernel<<<ggrid, 256, SM_TOTAL>>>(x);

    // ---- join: spmm needs both GEMM (main) and scatter (s2)
    cudaStreamWaitEvent(0, evJoin, 0);

    spmm_csr_kernel<<<(N_NODES * 32 + 255) / 256, 256>>>(out);

    colsumsq_kernel<<<(N_NODES + ROWS_PER_BLOCK - 1) / ROWS_PER_BLOCK, 256>>>(out, b);
    finalize_kernel<<<4096, 256>>>(out, b);
}

// round 10
// speedup vs baseline: 1.5759x; 1.2558x over previous
#include <cuda_runtime.h>
#include <cuda_bf16.h>
#include <cuda_fp16.h>
#include <cstdint>
#include <math.h>

#define N_NODES 100000
#define N_EDGES 3200000
#define D_IN    512
#define D_OUT   256
#define NB1     ((N_NODES + 1023) / 1024)   // 98 scan blocks

// Scratch (no cudaMalloc allowed)
__device__ __align__(16) __half g_presup[(size_t)N_NODES * D_OUT];  // 51.2 MB (fp16)
__device__ float g_colsum[D_OUT];
__device__ __align__(16) __nv_bfloat16 g_Wth[(size_t)D_OUT * D_IN]; // W^T hi [n][k]
__device__ __align__(16) __nv_bfloat16 g_Wtl[(size_t)D_OUT * D_IN]; // W^T lo [n][k]
// CSR binning scratch
__device__ int   g_counts[N_NODES];
__device__ int   g_rowptr[N_NODES + 1];
__device__ int   g_cursor[N_NODES];
__device__ int   g_blocksums[128];
__device__ __align__(16) int2 g_csr_pair[N_EDGES];   // (col, val bits)

__device__ __forceinline__ uint32_t smem_u32(const void* p) {
    uint32_t a;
    asm("{ .reg .u64 t; cvta.to.shared.u64 t, %1; cvt.u32.u64 %0, t; }" : "=r"(a) : "l"(p));
    return a;
}
__device__ __forceinline__ uint32_t pack_bf2(__nv_bfloat16 a, __nv_bfloat16 b) {
    __nv_bfloat162 t = __halves2bfloat162(a, b);
    return *reinterpret_cast<uint32_t*>(&t);
}
__device__ __forceinline__ void ldmatrix_x4(uint32_t* r, uint32_t addr) {
    asm volatile("ldmatrix.sync.aligned.m8n8.x4.shared.b16 {%0,%1,%2,%3}, [%4];"
                 : "=r"(r[0]), "=r"(r[1]), "=r"(r[2]), "=r"(r[3]) : "r"(addr));
}
__device__ __forceinline__ void mma_bf16(float* d, const uint32_t* a, const uint32_t* b) {
    asm volatile(
        "mma.sync.aligned.m16n8k16.row.col.f32.bf16.bf16.f32 "
        "{%0,%1,%2,%3}, {%4,%5,%6,%7}, {%8,%9}, {%0,%1,%2,%3};"
        : "+f"(d[0]), "+f"(d[1]), "+f"(d[2]), "+f"(d[3])
        : "r"(a[0]), "r"(a[1]), "r"(a[2]), "r"(a[3]), "r"(b[0]), "r"(b[1]));
}
__device__ __forceinline__ void cp_async16(uint32_t dst, const void* src) {
    asm volatile("cp.async.cg.shared.global [%0], [%1], 16;"
                 :: "r"(dst), "l"(__cvta_generic_to_global(src)) : "memory");
}
#define CP_COMMIT() asm volatile("cp.async.commit_group;" ::: "memory")

// ===========================================================================
// 0) W transpose + hi/lo bf16 split
// ===========================================================================
__global__ __launch_bounds__(256) void conv_w_kernel(const float* __restrict__ W) {
    int idx = blockIdx.x * 256 + threadIdx.x;
    if (idx >= D_IN * D_OUT) return;
    int k = idx / D_OUT, n = idx % D_OUT;
    float v = W[idx];
    __nv_bfloat16 h = __float2bfloat16_rn(v);
    __nv_bfloat16 l = __float2bfloat16_rn(v - __bfloat162float(h));
    g_Wth[(size_t)n * D_IN + k] = h;
    g_Wtl[(size_t)n * D_IN + k] = l;
}

// ===========================================================================
// 1) GEMM: pre_sup = x @ W via mma.sync bf16 hi/lo, 2-stage cp.async pipeline
//    Output stored as fp16.
// ===========================================================================
#define BM 128
#define BN 128
#define BK 32
#define NKC (D_IN / BK)     // 16 chunks
#define ROW_B 80
#define ST_A_HI 0
#define ST_A_LO 10240
#define ST_B_HI 20480
#define ST_B_LO 30720
#define STAGE_B 40960
#define SM_TOTAL (2 * STAGE_B)   // 81920

__global__ __launch_bounds__(256, 1) void gemm_tc_kernel(const float* __restrict__ x) {
    extern __shared__ __align__(16) char smem[];
    const uint32_t sbase = smem_u32(smem);

    const int tid = threadIdx.x;
    const int wid = tid >> 5;
    const int lane = tid & 31;
    const int n0 = blockIdx.x * BN;    // grid.x = 2: both N-blocks of an m-tile adjacent
    const int m0 = blockIdx.y * BM;
    const int warp_m = (wid & 1) * 64;
    const int warp_n = (wid >> 1) * 32;

    const int a_row = tid >> 3;
    const int a_f4  = tid & 7;
    float4 areg[4];

    float acc[4][4][4];
#pragma unroll
    for (int i = 0; i < 4; i++)
#pragma unroll
        for (int j = 0; j < 4; j++)
#pragma unroll
            for (int t = 0; t < 4; t++) acc[i][j][t] = 0.f;

    const uint32_t aLane = (uint32_t)((warp_m + (lane & 15)) * ROW_B + ((lane >> 4) << 4));
    const uint32_t bLane = (uint32_t)((warp_n + (lane & 7)) * ROW_B + ((lane >> 3) << 4));

    auto ldgA = [&](int kc) {
        const int k0 = kc * BK;
#pragma unroll
        for (int i = 0; i < 4; i++) {
            int row = a_row + i * 32;
            int m = m0 + row;
            areg[i] = make_float4(0.f, 0.f, 0.f, 0.f);
            if (m < N_NODES)
                areg[i] = *(const float4*)(x + (size_t)m * D_IN + k0 + a_f4 * 4);
        }
    };
    auto stsA = [&](int st) {
        char* sb = smem + st * STAGE_B;
#pragma unroll
        for (int i = 0; i < 4; i++) {
            float4 a = areg[i];
            int row = a_row + i * 32;
            __nv_bfloat16 h0 = __float2bfloat16_rn(a.x), h1 = __float2bfloat16_rn(a.y);
            __nv_bfloat16 h2 = __float2bfloat16_rn(a.z), h3 = __float2bfloat16_rn(a.w);
            __nv_bfloat16 l0 = __float2bfloat16_rn(a.x - __bfloat162float(h0));
            __nv_bfloat16 l1 = __float2bfloat16_rn(a.y - __bfloat162float(h1));
            __nv_bfloat16 l2 = __float2bfloat16_rn(a.z - __bfloat162float(h2));
            __nv_bfloat16 l3 = __float2bfloat16_rn(a.w - __bfloat162float(h3));
            int off = row * ROW_B + a_f4 * 8;
            *(uint2*)(sb + ST_A_HI + off) = make_uint2(pack_bf2(h0, h1), pack_bf2(h2, h3));
            *(uint2*)(sb + ST_A_LO + off) = make_uint2(pack_bf2(l0, l1), pack_bf2(l2, l3));
        }
    };
    auto cpB = [&](int kc, int st) {
        const int k0 = kc * BK;
        const uint32_t stb = sbase + st * STAGE_B;
#pragma unroll
        for (int i = 0; i < 4; i++) {
            int idx = tid + i * 256;
            int sub = idx & 511;
            int row = sub >> 2;
            int ch  = sub & 3;
            uint32_t off = (uint32_t)(row * ROW_B + ch * 16);
            if (idx < 512)
                cp_async16(stb + ST_B_HI + off, g_Wth + (size_t)(n0 + row) * D_IN + k0 + ch * 8);
            else
                cp_async16(stb + ST_B_LO + off, g_Wtl + (size_t)(n0 + row) * D_IN + k0 + ch * 8);
        }
        CP_COMMIT();
    };

    // ---- prologue
    ldgA(0);
    cpB(0, 0);
    stsA(0);
    ldgA(1);
    cpB(1, 1);
    asm volatile("cp.async.wait_group 1;" ::: "memory");
    __syncthreads();

    for (int kc = 0; kc < NKC; kc++) {
        const int cur = kc & 1;
        const uint32_t base = sbase + cur * STAGE_B;

        uint32_t bh[4][4], bl[4][4];
#pragma unroll
        for (int nt = 0; nt < 4; nt++) {
            ldmatrix_x4(bh[nt], base + ST_B_HI + bLane + nt * 8 * ROW_B);
            ldmatrix_x4(bl[nt], base + ST_B_LO + bLane + nt * 8 * ROW_B);
        }
#pragma unroll
        for (int ks = 0; ks < 2; ks++) {
            uint32_t ah[4][4], al[4][4];
#pragma unroll
            for (int mt = 0; mt < 4; mt++) {
                ldmatrix_x4(ah[mt], base + ST_A_HI + aLane + mt * 16 * ROW_B + ks * 32);
                ldmatrix_x4(al[mt], base + ST_A_LO + aLane + mt * 16 * ROW_B + ks * 32);
            }
#pragma unroll
            for (int mt = 0; mt < 4; mt++) {
#pragma unroll
                for (int nt = 0; nt < 4; nt++) {
                    uint32_t bhp[2] = {bh[nt][ks * 2], bh[nt][ks * 2 + 1]};
                    uint32_t blp[2] = {bl[nt][ks * 2], bl[nt][ks * 2 + 1]};
                    mma_bf16(acc[mt][nt], ah[mt], bhp);
                    mma_bf16(acc[mt][nt], ah[mt], blp);
                    mma_bf16(acc[mt][nt], al[mt], bhp);
                }
            }
        }

        if (kc < NKC - 1) stsA(cur ^ 1);
        __syncthreads();
        if (kc < NKC - 2) {
            ldgA(kc + 2);
            cpB(kc + 2, cur);
        }
        if (kc < NKC - 1) {
            if (kc < NKC - 2)
                asm volatile("cp.async.wait_group 1;" ::: "memory");
            else
                asm volatile("cp.async.wait_group 0;" ::: "memory");
            __syncthreads();
        }
    }

    // ---- epilogue: store fp16
    const int mrow = m0 + warp_m + (lane >> 2);
    const int ncol = n0 + warp_n + (lane & 3) * 2;
#pragma unroll
    for (int mt = 0; mt < 4; mt++) {
#pragma unroll
        for (int nt = 0; nt < 4; nt++) {
            int m = mrow + mt * 16;
            int n = ncol + nt * 8;
            if (m < N_NODES)
                *(__half2*)(g_presup + (size_t)m * D_OUT + n) =
                    __floats2half2_rn(acc[mt][nt][0], acc[mt][nt][1]);
            if (m + 8 < N_NODES)
                *(__half2*)(g_presup + (size_t)(m + 8) * D_OUT + n) =
                    __floats2half2_rn(acc[mt][nt][2], acc[mt][nt][3]);
        }
    }
}

// ===========================================================================
// 2a) CSR binning: count -> scan -> scatter
// ===========================================================================
__global__ __launch_bounds__(1024) void zero_counts_kernel() {
    int i = blockIdx.x * 1024 + threadIdx.x;
    if (i < N_NODES) g_counts[i] = 0;
}

__global__ __launch_bounds__(256) void count_kernel(const int* __restrict__ erow) {
    int e = blockIdx.x * 256 + threadIdx.x;
    if (e < N_EDGES) atomicAdd(&g_counts[__ldg(erow + e)], 1);
}

__global__ __launch_bounds__(1024) void scan1_kernel() {
    const int tid = threadIdx.x, lane = tid & 31, wid = tid >> 5;
    const int i = blockIdx.x * 1024 + tid;
    int v = (i < N_NODES) ? g_counts[i] : 0;
    int inc = v;
#pragma unroll
    for (int d = 1; d < 32; d <<= 1) {
        int t = __shfl_up_sync(~0u, inc, d);
        if (lane >= d) inc += t;
    }
    __shared__ int ws[32];
    if (lane == 31) ws[wid] = inc;
    __syncthreads();
    if (wid == 0) {
        int w = ws[lane];
#pragma unroll
        for (int d = 1; d < 32; d <<= 1) {
            int t = __shfl_up_sync(~0u, w, d);
            if (lane >= d) w += t;
        }
        ws[lane] = w;
    }
    __syncthreads();
    int base = wid ? ws[wid - 1] : 0;
    if (i < N_NODES) g_rowptr[i] = base + inc - v;
    if (tid == 0) g_blocksums[blockIdx.x] = ws[31];
}

__global__ __launch_bounds__(128) void scan2_kernel() {
    __shared__ int s[128];
    const int tid = threadIdx.x;
    s[tid] = (tid < NB1) ? g_blocksums[tid] : 0;
    __syncthreads();
    for (int d = 1; d < 128; d <<= 1) {
        int t = (tid >= d) ? s[tid - d] : 0;
        __syncthreads();
        s[tid] += t;
        __syncthreads();
    }
    g_blocksums[tid] = (tid > 0) ? s[tid - 1] : 0;
}

__global__ __launch_bounds__(1024) void scan3_kernel() {
    int i = blockIdx.x * 1024 + threadIdx.x;
    if (i < N_NODES) {
        int rp = g_rowptr[i] + g_blocksums[blockIdx.x];
        g_rowptr[i] = rp;
        g_cursor[i] = rp;
    }
    if (i == 0) g_rowptr[N_NODES] = N_EDGES;
}

__global__ __launch_bounds__(256) void scatter_kernel(const int* __restrict__ erow,
                                                      const int* __restrict__ ecol,
                                                      const float* __restrict__ evals) {
    int e = blockIdx.x * 256 + threadIdx.x;
    if (e >= N_EDGES) return;
    int r = __ldg(erow + e);
    int p = atomicAdd(&g_cursor[r], 1);
    g_csr_pair[p] = make_int2(__ldg(ecol + e), __float_as_int(__ldg(evals + e)));
}

// ===========================================================================
// 2b) SpMM CSR: one warp per row; fp16 gathers (one uint4 = 8 halves per lane)
// ===========================================================================
__global__ __launch_bounds__(256) void spmm_csr_kernel(float* __restrict__ out) {
    const int lane = threadIdx.x & 31;
    const int r = (blockIdx.x * 256 + threadIdx.x) >> 5;
    if (r >= N_NODES) return;
    const int beg = __ldg(g_rowptr + r);
    const int end = __ldg(g_rowptr + r + 1);

    float a[8] = {0.f, 0.f, 0.f, 0.f, 0.f, 0.f, 0.f, 0.f};
    const uint4* base = (const uint4*)g_presup;   // 32 uint4 per 256-half row

    int e = beg;
    for (; e + 2 <= end; e += 2) {
        int2 pr0 = __ldg(g_csr_pair + e);
        int2 pr1 = __ldg(g_csr_pair + e + 1);
        uint4 q0 = __ldg(base + (size_t)pr0.x * 32 + lane);
        uint4 q1 = __ldg(base + (size_t)pr1.x * 32 + lane);
        float v0 = __int_as_float(pr0.y);
        float v1 = __int_as_float(pr1.y);
        const __half2* h0 = (const __half2*)&q0;
        const __half2* h1 = (const __half2*)&q1;
#pragma unroll
        for (int j = 0; j < 4; j++) {
            float2 f0 = __half22float2(h0[j]);
            float2 f1 = __half22float2(h1[j]);
            a[j * 2 + 0] = fmaf(v0, f0.x, a[j * 2 + 0]);
            a[j * 2 + 1] = fmaf(v0, f0.y, a[j * 2 + 1]);
            a[j * 2 + 0] = fmaf(v1, f1.x, a[j * 2 + 0]);
            a[j * 2 + 1] = fmaf(v1, f1.y, a[j * 2 + 1]);
        }
    }
    if (e < end) {
        int2 pr0 = __ldg(g_csr_pair + e);
        uint4 q0 = __ldg(base + (size_t)pr0.x * 32 + lane);
        float v0 = __int_as_float(pr0.y);
        const __half2* h0 = (const __half2*)&q0;
#pragma unroll
        for (int j = 0; j < 4; j++) {
            float2 f0 = __half22float2(h0[j]);
            a[j * 2 + 0] = fmaf(v0, f0.x, a[j * 2 + 0]);
            a[j * 2 + 1] = fmaf(v0, f0.y, a[j * 2 + 1]);
        }
    }

    // columns lane*8 .. lane*8+7
    float4* dst = (float4*)(out + (size_t)r * D_OUT + lane * 8);
    dst[0] = make_float4(a[0], a[1], a[2], a[3]);
    dst[1] = make_float4(a[4], a[5], a[6], a[7]);
}

// ===========================================================================
// 3) Column sum-of-squares of (agg + b)
// ===========================================================================
#define ROWS_PER_BLOCK 256
__global__ __launch_bounds__(256) void colsumsq_kernel(const float* __restrict__ out,
                                                       const float* __restrict__ b) {
    const int c = threadIdx.x;
    const float bias = __ldg(b + c);
    const int r0 = blockIdx.x * ROWS_PER_BLOCK;
    const int r1 = min(r0 + ROWS_PER_BLOCK, N_NODES);
    float s = 0.f;
    for (int r = r0; r < r1; r++) {
        float v = out[(size_t)r * D_OUT + c] + bias;
        s = fmaf(v, v, s);
    }
    atomicAdd(&g_colsum[c], s);
}

__global__ void zero_colsum_kernel() { g_colsum[threadIdx.x] = 0.f; }

// ===========================================================================
// 4) Finalize: out = softplus((agg + b) / max(col_norm, 1e-12))
// ===========================================================================
__global__ __launch_bounds__(256) void finalize_kernel(float* __restrict__ out,
                                                       const float* __restrict__ b) {
    const int c = threadIdx.x;
    const float bias = __ldg(b + c);
    const float inv = 1.f / fmaxf(sqrtf(g_colsum[c]), 1e-12f);
    for (int r = blockIdx.x; r < N_NODES; r += gridDim.x) {
        float v = (out[(size_t)r * D_OUT + c] + bias) * inv;
        out[(size_t)r * D_OUT + c] = fmaxf(v, 0.f) + log1pf(__expf(-fabsf(v)));
    }
}

// ===========================================================================
extern "C" void kernel_launch(void* const* d_in, const int* in_sizes, int n_in,
                              void* d_out, int out_size) {
    const float* x     = (const float*)d_in[0];
    const int*   erow  = (const int*)  d_in[1];
    const int*   ecol  = (const int*)  d_in[2];
    const float* evals = (const float*)d_in[3];
    const float* W     = (const float*)d_in[4];
    const float* b     = (const float*)d_in[5];
    float* out = (float*)d_out;

    static cudaStream_t s2 = nullptr;
    static cudaEvent_t evFork = nullptr, evJoin = nullptr;
    if (!s2) {
        cudaStreamCreateWithFlags(&s2, cudaStreamNonBlocking);
        cudaEventCreateWithFlags(&evFork, cudaEventDisableTiming);
        cudaEventCreateWithFlags(&evJoin, cudaEventDisableTiming);
        cudaFuncSetAttribute(gemm_tc_kernel,
                             cudaFuncAttributeMaxDynamicSharedMemorySize, SM_TOTAL);
    }

    // ---- fork: binning chain on s2, GEMM path on main stream (0)
    cudaEventRecord(evFork, 0);
    cudaStreamWaitEvent(s2, evFork, 0);

    // s2: CSR binning (independent of W/x path)
    zero_counts_kernel<<<NB1, 1024, 0, s2>>>();
    count_kernel<<<(N_EDGES + 255) / 256, 256, 0, s2>>>(erow);
    scan1_kernel<<<NB1, 1024, 0, s2>>>();
    scan2_kernel<<<1, 128, 0, s2>>>();
    scan3_kernel<<<NB1, 1024, 0, s2>>>();
    scatter_kernel<<<(N_EDGES + 255) / 256, 256, 0, s2>>>(erow, ecol, evals);
    cudaEventRecord(evJoin, s2);

    // main: W conversion + GEMM
    zero_colsum_kernel<<<1, D_OUT>>>();
    conv_w_kernel<<<(D_IN * D_OUT + 255) / 256, 256>>>(W);
    dim3 ggrid(D_OUT / BN, (N_NODES + BM - 1) / BM);
    gemm_tc_kernel<<<ggrid, 256, SM_TOTAL>>>(x);

    // ---- join: spmm needs both GEMM (main) and scatter (s2)
    cudaStreamWaitEvent(0, evJoin, 0);

    spmm_csr_kernel<<<(N_NODES * 32 + 255) / 256, 256>>>(out);

    colsumsq_kernel<<<(N_NODES + ROWS_PER_BLOCK - 1) / ROWS_PER_BLOCK, 256>>>(out, b);
    finalize_kernel<<<4096, 256>>>(out, b);
}

// round 11
// speedup vs baseline: 2.2138x; 1.4049x over previous
#include <cuda_runtime.h>
#include <cuda_bf16.h>
#include <cuda_fp16.h>
#include <cstdint>
#include <math.h>

#define N_NODES 100000
#define N_EDGES 3200000
#define D_IN    512
#define D_OUT   256
#define NB1     ((N_NODES + 1023) / 1024)   // 98 scan blocks

// Scratch (no cudaMalloc allowed)
__device__ __align__(16) __half g_presup[(size_t)N_NODES * D_OUT];  // 51.2 MB (fp16)
__device__ float g_colsum[D_OUT];
__device__ __align__(16) __nv_bfloat16 g_Wt[(size_t)D_OUT * D_IN];  // W^T bf16 [n][k]
// CSR binning scratch
__device__ int   g_counts[N_NODES];
__device__ int   g_rowptr[N_NODES + 1];
__device__ int   g_cursor[N_NODES];
__device__ int   g_blocksums[128];
__device__ __align__(16) int2 g_csr_pair[N_EDGES];   // (col, val bits)

__device__ __forceinline__ uint32_t smem_u32(const void* p) {
    uint32_t a;
    asm("{ .reg .u64 t; cvta.to.shared.u64 t, %1; cvt.u32.u64 %0, t; }" : "=r"(a) : "l"(p));
    return a;
}
__device__ __forceinline__ uint32_t pack_bf2(__nv_bfloat16 a, __nv_bfloat16 b) {
    __nv_bfloat162 t = __halves2bfloat162(a, b);
    return *reinterpret_cast<uint32_t*>(&t);
}
__device__ __forceinline__ void ldmatrix_x4(uint32_t* r, uint32_t addr) {
    asm volatile("ldmatrix.sync.aligned.m8n8.x4.shared.b16 {%0,%1,%2,%3}, [%4];"
                 : "=r"(r[0]), "=r"(r[1]), "=r"(r[2]), "=r"(r[3]) : "r"(addr));
}
__device__ __forceinline__ void mma_bf16(float* d, const uint32_t* a, const uint32_t* b) {
    asm volatile(
        "mma.sync.aligned.m16n8k16.row.col.f32.bf16.bf16.f32 "
        "{%0,%1,%2,%3}, {%4,%5,%6,%7}, {%8,%9}, {%0,%1,%2,%3};"
        : "+f"(d[0]), "+f"(d[1]), "+f"(d[2]), "+f"(d[3])
        : "r"(a[0]), "r"(a[1]), "r"(a[2]), "r"(a[3]), "r"(b[0]), "r"(b[1]));
}
__device__ __forceinline__ void cp_async16(uint32_t dst, const void* src) {
    asm volatile("cp.async.cg.shared.global [%0], [%1], 16;"
                 :: "r"(dst), "l"(__cvta_generic_to_global(src)) : "memory");
}
#define CP_COMMIT() asm volatile("cp.async.commit_group;" ::: "memory")

// ===========================================================================
// 0) W transpose to bf16:  g_Wt[n][k] = bf16(W[k][n])
// ===========================================================================
__global__ __launch_bounds__(256) void conv_w_kernel(const float* __restrict__ W) {
    int idx = blockIdx.x * 256 + threadIdx.x;
    if (idx >= D_IN * D_OUT) return;
    int k = idx / D_OUT, n = idx % D_OUT;
    g_Wt[(size_t)n * D_IN + k] = __float2bfloat16_rn(W[idx]);
}

// ===========================================================================
// 1) GEMM: pre_sup = x @ W, pure bf16 mma.sync, 2-stage cp.async pipeline,
//    2 CTAs/SM. Output fp16.
// ===========================================================================
#define BM 128
#define BN 128
#define BK 32
#define NKC (D_IN / BK)     // 16 chunks
#define ROW_B 80
#define ST_A 0
#define ST_B 10240
#define STAGE_B 20480
#define SM_TOTAL (2 * STAGE_B)   // 40960 per CTA

__global__ __launch_bounds__(256, 2) void gemm_tc_kernel(const float* __restrict__ x) {
    extern __shared__ __align__(16) char smem[];
    const uint32_t sbase = smem_u32(smem);

    const int tid = threadIdx.x;
    const int wid = tid >> 5;
    const int lane = tid & 31;
    const int n0 = blockIdx.x * BN;    // grid.x = 2: both N-blocks of an m-tile adjacent
    const int m0 = blockIdx.y * BM;
    const int warp_m = (wid & 1) * 64;
    const int warp_n = (wid >> 1) * 32;

    const int a_row = tid >> 3;
    const int a_f4  = tid & 7;
    float4 areg[4];

    float acc[4][4][4];
#pragma unroll
    for (int i = 0; i < 4; i++)
#pragma unroll
        for (int j = 0; j < 4; j++)
#pragma unroll
            for (int t = 0; t < 4; t++) acc[i][j][t] = 0.f;

    const uint32_t aLane = (uint32_t)((warp_m + (lane & 15)) * ROW_B + ((lane >> 4) << 4));
    const uint32_t bLane = (uint32_t)((warp_n + (lane & 7)) * ROW_B + ((lane >> 3) << 4));

    auto ldgA = [&](int kc) {
        const int k0 = kc * BK;
#pragma unroll
        for (int i = 0; i < 4; i++) {
            int row = a_row + i * 32;
            int m = m0 + row;
            areg[i] = make_float4(0.f, 0.f, 0.f, 0.f);
            if (m < N_NODES)
                areg[i] = *(const float4*)(x + (size_t)m * D_IN + k0 + a_f4 * 4);
        }
    };
    auto stsA = [&](int st) {
        char* sb = smem + st * STAGE_B;
#pragma unroll
        for (int i = 0; i < 4; i++) {
            float4 a = areg[i];
            int row = a_row + i * 32;
            __nv_bfloat16 h0 = __float2bfloat16_rn(a.x), h1 = __float2bfloat16_rn(a.y);
            __nv_bfloat16 h2 = __float2bfloat16_rn(a.z), h3 = __float2bfloat16_rn(a.w);
            *(uint2*)(sb + ST_A + row * ROW_B + a_f4 * 8) =
                make_uint2(pack_bf2(h0, h1), pack_bf2(h2, h3));
        }
    };
    auto cpB = [&](int kc, int st) {
        const int k0 = kc * BK;
        const uint32_t stb = sbase + st * STAGE_B;
#pragma unroll
        for (int i = 0; i < 2; i++) {
            int idx = tid + i * 256;       // 0..511
            int row = idx >> 2;
            int ch  = idx & 3;
            uint32_t off = (uint32_t)(row * ROW_B + ch * 16);
            cp_async16(stb + ST_B + off, g_Wt + (size_t)(n0 + row) * D_IN + k0 + ch * 8);
        }
        CP_COMMIT();
    };

    // ---- prologue
    ldgA(0);
    cpB(0, 0);
    stsA(0);
    ldgA(1);
    cpB(1, 1);
    asm volatile("cp.async.wait_group 1;" ::: "memory");
    __syncthreads();

    for (int kc = 0; kc < NKC; kc++) {
        const int cur = kc & 1;
        const uint32_t base = sbase + cur * STAGE_B;

        uint32_t bh[4][4];
#pragma unroll
        for (int nt = 0; nt < 4; nt++)
            ldmatrix_x4(bh[nt], base + ST_B + bLane + nt * 8 * ROW_B);
#pragma unroll
        for (int ks = 0; ks < 2; ks++) {
            uint32_t ah[4][4];
#pragma unroll
            for (int mt = 0; mt < 4; mt++)
                ldmatrix_x4(ah[mt], base + ST_A + aLane + mt * 16 * ROW_B + ks * 32);
#pragma unroll
            for (int mt = 0; mt < 4; mt++) {
#pragma unroll
                for (int nt = 0; nt < 4; nt++) {
                    uint32_t bhp[2] = {bh[nt][ks * 2], bh[nt][ks * 2 + 1]};
                    mma_bf16(acc[mt][nt], ah[mt], bhp);
                }
            }
        }

        if (kc < NKC - 1) stsA(cur ^ 1);
        __syncthreads();
        if (kc < NKC - 2) {
            ldgA(kc + 2);
            cpB(kc + 2, cur);
        }
        if (kc < NKC - 1) {
            if (kc < NKC - 2)
                asm volatile("cp.async.wait_group 1;" ::: "memory");
            else
                asm volatile("cp.async.wait_group 0;" ::: "memory");
            __syncthreads();
        }
    }

    // ---- epilogue: store fp16
    const int mrow = m0 + warp_m + (lane >> 2);
    const int ncol = n0 + warp_n + (lane & 3) * 2;
#pragma unroll
    for (int mt = 0; mt < 4; mt++) {
#pragma unroll
        for (int nt = 0; nt < 4; nt++) {
            int m = mrow + mt * 16;
            int n = ncol + nt * 8;
            if (m < N_NODES)
                *(__half2*)(g_presup + (size_t)m * D_OUT + n) =
                    __floats2half2_rn(acc[mt][nt][0], acc[mt][nt][1]);
            if (m + 8 < N_NODES)
                *(__half2*)(g_presup + (size_t)(m + 8) * D_OUT + n) =
                    __floats2half2_rn(acc[mt][nt][2], acc[mt][nt][3]);
        }
    }
}

// ===========================================================================
// 2a) CSR binning: count -> scan -> scatter
// ===========================================================================
__global__ __launch_bounds__(1024) void zero_counts_kernel() {
    int i = blockIdx.x * 1024 + threadIdx.x;
    if (i < N_NODES) g_counts[i] = 0;
}

__global__ __launch_bounds__(256) void count_kernel(const int* __restrict__ erow) {
    int e = blockIdx.x * 256 + threadIdx.x;
    if (e < N_EDGES) atomicAdd(&g_counts[__ldg(erow + e)], 1);
}

__global__ __launch_bounds__(1024) void scan1_kernel() {
    const int tid = threadIdx.x, lane = tid & 31, wid = tid >> 5;
    const int i = blockIdx.x * 1024 + tid;
    int v = (i < N_NODES) ? g_counts[i] : 0;
    int inc = v;
#pragma unroll
    for (int d = 1; d < 32; d <<= 1) {
        int t = __shfl_up_sync(~0u, inc, d);
        if (lane >= d) inc += t;
    }
    __shared__ int ws[32];
    if (lane == 31) ws[wid] = inc;
    __syncthreads();
    if (wid == 0) {
        int w = ws[lane];
#pragma unroll
        for (int d = 1; d < 32; d <<= 1) {
            int t = __shfl_up_sync(~0u, w, d);
            if (lane >= d) w += t;
        }
        ws[lane] = w;
    }
    __syncthreads();
    int base = wid ? ws[wid - 1] : 0;
    if (i < N_NODES) g_rowptr[i] = base + inc - v;
    if (tid == 0) g_blocksums[blockIdx.x] = ws[31];
}

__global__ __launch_bounds__(128) void scan2_kernel() {
    __shared__ int s[128];
    const int tid = threadIdx.x;
    s[tid] = (tid < NB1) ? g_blocksums[tid] : 0;
    __syncthreads();
    for (int d = 1; d < 128; d <<= 1) {
        int t = (tid >= d) ? s[tid - d] : 0;
        __syncthreads();
        s[tid] += t;
        __syncthreads();
    }
    g_blocksums[tid] = (tid > 0) ? s[tid - 1] : 0;
}

__global__ __launch_bounds__(1024) void scan3_kernel() {
    int i = blockIdx.x * 1024 + threadIdx.x;
    if (i < N_NODES) {
        int rp = g_rowptr[i] + g_blocksums[blockIdx.x];
        g_rowptr[i] = rp;
        g_cursor[i] = rp;
    }
    if (i == 0) g_rowptr[N_NODES] = N_EDGES;
}

__global__ __launch_bounds__(256) void scatter_kernel(const int* __restrict__ erow,
                                                      const int* __restrict__ ecol,
                                                      const float* __restrict__ evals) {
    int e = blockIdx.x * 256 + threadIdx.x;
    if (e >= N_EDGES) return;
    int r = __ldg(erow + e);
    int p = atomicAdd(&g_cursor[r], 1);
    g_csr_pair[p] = make_int2(__ldg(ecol + e), __float_as_int(__ldg(evals + e)));
}

// ===========================================================================
// 2b) SpMM CSR: one warp per row; fp16 gathers (one uint4 = 8 halves per lane)
// ===========================================================================
__global__ __launch_bounds__(256) void spmm_csr_kernel(float* __restrict__ out) {
    const int lane = threadIdx.x & 31;
    const int r = (blockIdx.x * 256 + threadIdx.x) >> 5;
    if (r >= N_NODES) return;
    const int beg = __ldg(g_rowptr + r);
    const int end = __ldg(g_rowptr + r + 1);

    float a[8] = {0.f, 0.f, 0.f, 0.f, 0.f, 0.f, 0.f, 0.f};
    const uint4* base = (const uint4*)g_presup;   // 32 uint4 per 256-half row

    int e = beg;
    for (; e + 2 <= end; e += 2) {
        int2 pr0 = __ldg(g_csr_pair + e);
        int2 pr1 = __ldg(g_csr_pair + e + 1);
        uint4 q0 = __ldg(base + (size_t)pr0.x * 32 + lane);
        uint4 q1 = __ldg(base + (size_t)pr1.x * 32 + lane);
        float v0 = __int_as_float(pr0.y);
        float v1 = __int_as_float(pr1.y);
        const __half2* h0 = (const __half2*)&q0;
        const __half2* h1 = (const __half2*)&q1;
#pragma unroll
        for (int j = 0; j < 4; j++) {
            float2 f0 = __half22float2(h0[j]);
            float2 f1 = __half22float2(h1[j]);
            a[j * 2 + 0] = fmaf(v0, f0.x, a[j * 2 + 0]);
            a[j * 2 + 1] = fmaf(v0, f0.y, a[j * 2 + 1]);
            a[j * 2 + 0] = fmaf(v1, f1.x, a[j * 2 + 0]);
            a[j * 2 + 1] = fmaf(v1, f1.y, a[j * 2 + 1]);
        }
    }
    if (e < end) {
        int2 pr0 = __ldg(g_csr_pair + e);
        uint4 q0 = __ldg(base + (size_t)pr0.x * 32 + lane);
        float v0 = __int_as_float(pr0.y);
        const __half2* h0 = (const __half2*)&q0;
#pragma unroll
        for (int j = 0; j < 4; j++) {
            float2 f0 = __half22float2(h0[j]);
            a[j * 2 + 0] = fmaf(v0, f0.x, a[j * 2 + 0]);
            a[j * 2 + 1] = fmaf(v0, f0.y, a[j * 2 + 1]);
        }
    }

    float4* dst = (float4*)(out + (size_t)r * D_OUT + lane * 8);
    dst[0] = make_float4(a[0], a[1], a[2], a[3]);
    dst[1] = make_float4(a[4], a[5], a[6], a[7]);
}

// ===========================================================================
// 3) Column sum-of-squares of (agg + b)
// ===========================================================================
#define ROWS_PER_BLOCK 256
__global__ __launch_bounds__(256) void colsumsq_kernel(const float* __restrict__ out,
                                                       const float* __restrict__ b) {
    const int c = threadIdx.x;
    const float bias = __ldg(b + c);
    const int r0 = blockIdx.x * ROWS_PER_BLOCK;
    const int r1 = min(r0 + ROWS_PER_BLOCK, N_NODES);
    float s = 0.f;
    for (int r = r0; r < r1; r++) {
        float v = out[(size_t)r * D_OUT + c] + bias;
        s = fmaf(v, v, s);
    }
    atomicAdd(&g_colsum[c], s);
}

__global__ void zero_colsum_kernel() { g_colsum[threadIdx.x] = 0.f; }

// ===========================================================================
// 4) Finalize: out = softplus((agg + b) / max(col_norm, 1e-12))
// ===========================================================================
__global__ __launch_bounds__(256) void finalize_kernel(float* __restrict__ out,
                                                       const float* __restrict__ b) {
    const int c = threadIdx.x;
    const float bias = __ldg(b + c);
    const float inv = 1.f / fmaxf(sqrtf(g_colsum[c]), 1e-12f);
    for (int r = blockIdx.x; r < N_NODES; r += gridDim.x) {
        float v = (out[(size_t)r * D_OUT + c] + bias) * inv;
        out[(size_t)r * D_OUT + c] = fmaxf(v, 0.f) + log1pf(__expf(-fabsf(v)));
    }
}

// ===========================================================================
extern "C" void kernel_launch(void* const* d_in, const int* in_sizes, int n_in,
                              void* d_out, int out_size) {
    const float* x     = (const float*)d_in[0];
    const int*   erow  = (const int*)  d_in[1];
    const int*   ecol  = (const int*)  d_in[2];
    const float* evals = (const float*)d_in[3];
    const float* W     = (const float*)d_in[4];
    const float* b     = (const float*)d_in[5];
    float* out = (float*)d_out;

    static cudaStream_t s2 = nullptr;
    static cudaEvent_t evFork = nullptr, evJoin = nullptr;
    if (!s2) {
        cudaStreamCreateWithFlags(&s2, cudaStreamNonBlocking);
        cudaEventCreateWithFlags(&evFork, cudaEventDisableTiming);
        cudaEventCreateWithFlags(&evJoin, cudaEventDisableTiming);
        cudaFuncSetAttribute(gemm_tc_kernel,
                             cudaFuncAttributeMaxDynamicSharedMemorySize, SM_TOTAL);
    }

    // ---- fork: binning chain on s2, GEMM path on main stream (0)
    cudaEventRecord(evFork, 0);
    cudaStreamWaitEvent(s2, evFork, 0);

    // s2: CSR binning (independent of W/x path)
    zero_counts_kernel<<<NB1, 1024, 0, s2>>>();
    count_kernel<<<(N_EDGES + 255) / 256, 256, 0, s2>>>(erow);
    scan1_kernel<<<NB1, 1024, 0, s2>>>();
    scan2_kernel<<<1, 128, 0, s2>>>();
    scan3_kernel<<<NB1, 1024, 0, s2>>>();
    scatter_kernel<<<(N_EDGES + 255) / 256, 256, 0, s2>>>(erow, ecol, evals);
    cudaEventRecord(evJoin, s2);

    // main: W conversion + GEMM
    zero_colsum_kernel<<<1, D_OUT>>>();
    conv_w_kernel<<<(D_IN * D_OUT + 255) / 256, 256>>>(W);
    dim3 ggrid(D_OUT / BN, (N_NODES + BM - 1) / BM);
    gemm_tc_kernel<<<ggrid, 256, SM_TOTAL>>>(x);

    // ---- join: spmm needs both GEMM (main) and scatter (s2)
    cudaStreamWaitEvent(0, evJoin, 0);

    spmm_csr_kernel<<<(N_NODES * 32 + 255) / 256, 256>>>(out);

    colsumsq_kernel<<<(N_NODES + ROWS_PER_BLOCK - 1) / ROWS_PER_BLOCK, 256>>>(out, b);
    finalize_kernel<<<4096, 256>>>(out, b);
}